// round 5
// baseline (speedup 1.0000x reference)
#include <cuda.h>
#include <cuda_runtime.h>
#include <cuda_bf16.h>
#include <math.h>
#include <stdint.h>

// Problem constants
#define DIMN     5120
#define NHEADS   40
#define HDIM     128
#define BATCH    2
#define SEQ      1024
#define TOKENS   (BATCH * SEQ)        // 2048
#define QKV_COLS (3 * DIMN)           // 15360
#define EPSV     1e-6f
#define SCALEV   0.08838834764831845f // 128^-0.5

// GEMM tiling: CTA 128x256, BK=64, 2-stage TMA pipeline, 8 warps of 64x64
#define GBM 128
#define GBN 256
#define GBK 64
#define A_PL (GBM * GBK * 2)              // 16384 bytes (one bf16 plane)
#define B_PL (GBN * GBK * 2)              // 32768
#define STB  (2 * A_PL + 2 * B_PL)        // 98304 per stage
#define GSMEM (2048 + 2 * STB)            // align slack + ctrl + 2 stages
#define NCH (DIMN / GBK)                  // 80

// Scratch (no allocations allowed)
__device__ float          g_qkv[(size_t)TOKENS * QKV_COLS];
__device__ __nv_bfloat16  g_xhi[(size_t)TOKENS * DIMN];
__device__ __nv_bfloat16  g_xlo[(size_t)TOKENS * DIMN];
__device__ __nv_bfloat16  g_ahi[(size_t)TOKENS * DIMN];
__device__ __nv_bfloat16  g_alo[(size_t)TOKENS * DIMN];
__device__ __nv_bfloat16  g_wqhi[(size_t)QKV_COLS * DIMN];
__device__ __nv_bfloat16  g_wqlo[(size_t)QKV_COLS * DIMN];
__device__ __nv_bfloat16  g_wohi[(size_t)DIMN * DIMN];
__device__ __nv_bfloat16  g_wolo[(size_t)DIMN * DIMN];

// ---------------------------------------------------------------------------
__device__ __forceinline__ uint32_t smem_u32(const void* p) {
    uint32_t a;
    asm("{ .reg .u64 t; cvta.to.shared.u64 t, %1; cvt.u32.u64 %0, t; }" : "=r"(a) : "l"(p));
    return a;
}
#define MBARRIER_INIT(addr, cnt) \
    asm volatile("mbarrier.init.shared.b64 [%0], %1;" :: "r"(addr), "r"(cnt) : "memory")
#define MBARRIER_EXPECT_TX(addr, bytes) \
    asm volatile("mbarrier.arrive.expect_tx.shared.b64 _, [%0], %1;" :: "r"(addr), "r"(bytes) : "memory")
#define MBARRIER_WAIT_PARITY(addr, parity) do { \
    uint32_t _m = (addr); uint32_t _p = (parity); uint32_t _d; \
    asm volatile("{\n\t.reg .pred p;\n\t" \
        "mbarrier.try_wait.parity.acquire.cta.shared::cta.b64 p, [%1], %2;\n\t" \
        "selp.b32 %0, 1, 0, p;\n\t}" : "=r"(_d) : "r"(_m), "r"(_p) : "memory"); \
    if (!_d) { \
        asm volatile("{\n\t.reg .pred P1;\n\t" \
            "WL_%=:\n\t" \
            "mbarrier.try_wait.parity.acquire.cta.shared::cta.b64 P1, [%0], %1, 0x989680;\n\t" \
            "@P1 bra.uni WD_%=;\n\t" \
            "bra.uni WL_%=;\n\t" \
            "WD_%=:\n\t}" :: "r"(_m), "r"(_p) : "memory"); \
    } \
} while (0)
#define TMA_LOAD_2D(saddr, tmap, cx, cy, mbar) \
    asm volatile("cp.async.bulk.tensor.2d.shared::cta.global.tile.mbarrier::complete_tx::bytes " \
                 "[%0], [%1, {%2, %3}], [%4];" \
                 :: "r"(saddr), "l"(tmap), "r"(cx), "r"(cy), "r"(mbar) : "memory")

__device__ __forceinline__ void mma_bf16(float* c, const uint32_t* a, const uint32_t* b) {
    asm volatile("mma.sync.aligned.m16n8k16.row.col.f32.bf16.bf16.f32 "
        "{%0,%1,%2,%3}, {%4,%5,%6,%7}, {%8,%9}, {%0,%1,%2,%3};"
        : "+f"(c[0]), "+f"(c[1]), "+f"(c[2]), "+f"(c[3])
        : "r"(a[0]), "r"(a[1]), "r"(a[2]), "r"(a[3]), "r"(b[0]), "r"(b[1]));
}

// ---------------------------------------------------------------------------
// GEMM: C[M, Ntot] = A @ B^T + bias, 3-pass split bf16 (hh + hl + lh).
// Tiles loaded by TMA with SW128 swizzle; rows are GBK*2 = 128 bytes.
// Swizzled offset within a plane: r*128 + (c ^ ((r&7)*16)).
// grid (M/128, Ntot/256), 256 threads.
// ---------------------------------------------------------------------------
__global__ __launch_bounds__(256, 1) void gemm_tma(
    const __grid_constant__ CUtensorMap tAh, const __grid_constant__ CUtensorMap tAl,
    const __grid_constant__ CUtensorMap tBh, const __grid_constant__ CUtensorMap tBl,
    const float* __restrict__ bias, float* __restrict__ C, int Ntot)
{
    extern __shared__ char gsm[];
    const uint32_t sb0  = smem_u32(gsm);
    const uint32_t ctrl = (sb0 + 1023) & ~1023u;   // 1KB-aligned ctrl block
    const uint32_t tile = ctrl + 1024;             // stages (1KB aligned)
    char* tp = gsm + (tile - sb0);

    const int tid = threadIdx.x;
    const int m0  = blockIdx.x * GBM;
    const int n0  = blockIdx.y * GBN;
    const int wid = tid >> 5, lane = tid & 31;
    const int wm  = wid & 1;         // 2 groups of 64 rows
    const int wn  = wid >> 1;        // 4 groups of 64 cols
    const int gid = lane >> 2;       // 0..7
    const int tig = lane & 3;        // 0..3
    const int xorv = gid * 16;       // SW128 xor for this lane's rows (r&7 == gid)

    if (tid == 0) { MBARRIER_INIT(ctrl, 1); MBARRIER_INIT(ctrl + 8, 1); }
    __syncthreads();

    auto issue = [&](int s, int k0) {
        if (tid == 0) {
            const uint32_t st = tile + s * STB;
            MBARRIER_EXPECT_TX(ctrl + s * 8, STB);
            TMA_LOAD_2D(st,                  &tAh, k0, m0, ctrl + s * 8);
            TMA_LOAD_2D(st + A_PL,           &tAl, k0, m0, ctrl + s * 8);
            TMA_LOAD_2D(st + 2 * A_PL,       &tBh, k0, n0, ctrl + s * 8);
            TMA_LOAD_2D(st + 2 * A_PL + B_PL, &tBl, k0, n0, ctrl + s * 8);
        }
    };

    float acc[4][8][4];
#pragma unroll
    for (int a = 0; a < 4; ++a)
#pragma unroll
        for (int b = 0; b < 8; ++b)
#pragma unroll
            for (int c = 0; c < 4; ++c) acc[a][b][c] = 0.0f;

    issue(0, 0);
    issue(1, GBK);

    for (int it = 0; it < NCH; ++it) {
        const int s = it & 1;
        MBARRIER_WAIT_PARITY(ctrl + s * 8, (it >> 1) & 1);
        const char* st = tp + s * STB;

#pragma unroll
        for (int ks = 0; ks < 4; ++ks) {
            const int c0 = ks * 32 + tig * 4;
            const int ca = c0 ^ xorv;
            const int cb = (c0 + 16) ^ xorv;

            uint32_t ah[4][4], al[4][4];
#pragma unroll
            for (int mt = 0; mt < 4; ++mt) {
                const int r = wm * 64 + mt * 16 + gid;
                const char* p = st + r * 128;
                ah[mt][0] = *(const uint32_t*)(p + ca);
                ah[mt][1] = *(const uint32_t*)(p + 8 * 128 + ca);
                ah[mt][2] = *(const uint32_t*)(p + cb);
                ah[mt][3] = *(const uint32_t*)(p + 8 * 128 + cb);
                const char* q = p + A_PL;
                al[mt][0] = *(const uint32_t*)(q + ca);
                al[mt][1] = *(const uint32_t*)(q + 8 * 128 + ca);
                al[mt][2] = *(const uint32_t*)(q + cb);
                al[mt][3] = *(const uint32_t*)(q + 8 * 128 + cb);
            }
            uint32_t bh[8][2], bl[8][2];
#pragma unroll
            for (int nt = 0; nt < 8; ++nt) {
                const int r = wn * 64 + nt * 8 + gid;
                const char* p = st + 2 * A_PL + r * 128;
                bh[nt][0] = *(const uint32_t*)(p + ca);
                bh[nt][1] = *(const uint32_t*)(p + cb);
                const char* q = p + B_PL;
                bl[nt][0] = *(const uint32_t*)(q + ca);
                bl[nt][1] = *(const uint32_t*)(q + cb);
            }
            // pass-major: consecutive MMAs hit different accumulators
#pragma unroll
            for (int mt = 0; mt < 4; ++mt)
#pragma unroll
                for (int nt = 0; nt < 8; ++nt)
                    mma_bf16(acc[mt][nt], ah[mt], bh[nt]);
#pragma unroll
            for (int mt = 0; mt < 4; ++mt)
#pragma unroll
                for (int nt = 0; nt < 8; ++nt)
                    mma_bf16(acc[mt][nt], ah[mt], bl[nt]);
#pragma unroll
            for (int mt = 0; mt < 4; ++mt)
#pragma unroll
                for (int nt = 0; nt < 8; ++nt)
                    mma_bf16(acc[mt][nt], al[mt], bh[nt]);
        }
        __syncthreads();                 // all warps done with stage s
        if (it + 2 < NCH) issue(s, (it + 2) * GBK);
    }

    // epilogue
#pragma unroll
    for (int mt = 0; mt < 4; ++mt) {
#pragma unroll
        for (int nt = 0; nt < 8; ++nt) {
            const int row = m0 + wm * 64 + mt * 16 + gid;
            const int col = n0 + wn * 64 + nt * 8 + tig * 2;
            const float b0 = bias[col], b1 = bias[col + 1];
            float2 v0 = {acc[mt][nt][0] + b0, acc[mt][nt][1] + b1};
            float2 v1 = {acc[mt][nt][2] + b0, acc[mt][nt][3] + b1};
            *(float2*)(C + (size_t)row * Ntot + col)       = v0;
            *(float2*)(C + (size_t)(row + 8) * Ntot + col) = v1;
        }
    }
}

// ---------------------------------------------------------------------------
// elementwise split fp32 -> bf16 hi/lo
// ---------------------------------------------------------------------------
__global__ __launch_bounds__(256) void split_bf16(
    const float4* __restrict__ in, uint2* __restrict__ hi, uint2* __restrict__ lo, int n4)
{
    const int i = blockIdx.x * 256 + threadIdx.x;
    if (i >= n4) return;
    float4 v = in[i];
    __nv_bfloat16 h[4], l[4];
    float f[4] = {v.x, v.y, v.z, v.w};
#pragma unroll
    for (int j = 0; j < 4; ++j) {
        h[j] = __float2bfloat16_rn(f[j]);
        l[j] = __float2bfloat16_rn(f[j] - __bfloat162float(h[j]));
    }
    uint2 H, L;
    H.x = ((uint32_t)__bfloat16_as_ushort(h[1]) << 16) | __bfloat16_as_ushort(h[0]);
    H.y = ((uint32_t)__bfloat16_as_ushort(h[3]) << 16) | __bfloat16_as_ushort(h[2]);
    L.x = ((uint32_t)__bfloat16_as_ushort(l[1]) << 16) | __bfloat16_as_ushort(l[0]);
    L.y = ((uint32_t)__bfloat16_as_ushort(l[3]) << 16) | __bfloat16_as_ushort(l[2]);
    hi[i] = H;
    lo[i] = L;
}

// ---------------------------------------------------------------------------
// transpose + split: W [K,N] fp32 -> Whi/Wlo [N,K] bf16
// ---------------------------------------------------------------------------
__global__ __launch_bounds__(256) void transpose_split(
    const float* __restrict__ W,
    __nv_bfloat16* __restrict__ Whi, __nv_bfloat16* __restrict__ Wlo, int K, int N)
{
    __shared__ float t[32][33];
    const int n0 = blockIdx.x * 32, k0 = blockIdx.y * 32;
    const int tx = threadIdx.x, ty = threadIdx.y;
#pragma unroll
    for (int i = 0; i < 32; i += 8)
        t[ty + i][tx] = W[(size_t)(k0 + ty + i) * N + n0 + tx];
    __syncthreads();
#pragma unroll
    for (int i = 0; i < 32; i += 8) {
        float x = t[tx][ty + i];
        __nv_bfloat16 h = __float2bfloat16_rn(x);
        __nv_bfloat16 l = __float2bfloat16_rn(x - __bfloat162float(h));
        const size_t idx = (size_t)(n0 + ty + i) * K + k0 + tx;
        Whi[idx] = h;
        Wlo[idx] = l;
    }
}

// ---------------------------------------------------------------------------
// Fused RMSNorm + rotary, in place on q,k of g_qkv. One block per token.
// ---------------------------------------------------------------------------
__global__ __launch_bounds__(256) void rms_rope(
    float* __restrict__ qkv,
    const float* __restrict__ gq, const float* __restrict__ gk,
    const float* __restrict__ fcos, const float* __restrict__ fsin)
{
    const int t   = blockIdx.x;
    const int l   = t & (SEQ - 1);
    const int tid = threadIdx.x;

    float* qrow = qkv + (size_t)t * QKV_COLS;
    float* krow = qrow + DIMN;

    float sq = 0.0f, sk = 0.0f;
    for (int i = tid; i < DIMN; i += 256) {
        float a = qrow[i]; sq = fmaf(a, a, sq);
        float b = krow[i]; sk = fmaf(b, b, sk);
    }
#pragma unroll
    for (int off = 16; off; off >>= 1) {
        sq += __shfl_xor_sync(0xffffffffu, sq, off);
        sk += __shfl_xor_sync(0xffffffffu, sk, off);
    }
    __shared__ float redq[8], redk[8];
    __shared__ float bq, bk;
    const int warp = tid >> 5, lane = tid & 31;
    if (lane == 0) { redq[warp] = sq; redk[warp] = sk; }
    __syncthreads();
    if (tid == 0) {
        float a = 0.0f, b = 0.0f;
#pragma unroll
        for (int w = 0; w < 8; ++w) { a += redq[w]; b += redk[w]; }
        bq = a; bk = b;
    }
    __syncthreads();
    const float rq = rsqrtf(bq * (1.0f / DIMN) + EPSV);
    const float rk = rsqrtf(bk * (1.0f / DIMN) + EPSV);

    for (int p = tid; p < DIMN / 2; p += 256) {
        const int head = p >> 6;
        const int i2   = (p & 63) * 2;
        const int ce   = head * HDIM + i2;
        const int co   = ce + 1;
        const float ccos = fcos[l * HDIM + i2];
        const float csin = fsin[l * HDIM + i2 + 1];

        float xe = qrow[ce] * rq * gq[ce];
        float xo = qrow[co] * rq * gq[co];
        qrow[ce] = xe * ccos - xo * csin;
        qrow[co] = xe * csin + xo * ccos;

        xe = krow[ce] * rk * gk[ce];
        xo = krow[co] * rk * gk[co];
        krow[ce] = xe * ccos - xo * csin;
        krow[co] = xe * csin + xo * ccos;
    }
}

// ---------------------------------------------------------------------------
// Flash attention, fp32, Br=Bc=32, D=128. Epilogue emits bf16 hi/lo planes.
// ---------------------------------------------------------------------------
#define BR 32
#define BC 32
__global__ __launch_bounds__(256) void flash_attn(
    const float* __restrict__ qkv,
    __nv_bfloat16* __restrict__ ohi, __nv_bfloat16* __restrict__ olo)
{
    __shared__ float Qs[BR][132];
    __shared__ float KVs[BC][132];
    __shared__ float Ps[BR][36];

    const int qb  = blockIdx.x;
    const int bh  = blockIdx.y;
    const int b   = bh / NHEADS;
    const int h   = bh % NHEADS;
    const int tid = threadIdx.x;
    const int tr  = tid >> 4;
    const int tc  = tid & 15;

    const size_t rs = QKV_COLS;
    const float* qbase = qkv + (size_t)(b * SEQ + qb * BR) * rs + h * HDIM;

    for (int i = tid; i < BR * (HDIM / 4); i += 256) {
        const int r = i >> 5, c4 = (i & 31) * 4;
        float4 v = *(const float4*)(qbase + (size_t)r * rs + c4);
        Qs[r][c4]     = v.x * SCALEV;
        Qs[r][c4 + 1] = v.y * SCALEV;
        Qs[r][c4 + 2] = v.z * SCALEV;
        Qs[r][c4 + 3] = v.w * SCALEV;
    }

    float m_i[2] = {-INFINITY, -INFINITY};
    float l_i[2] = {0.0f, 0.0f};
    float o[2][8];
#pragma unroll
    for (int i = 0; i < 2; ++i)
#pragma unroll
        for (int c = 0; c < 8; ++c) o[i][c] = 0.0f;

    for (int kb = 0; kb < SEQ / BC; ++kb) {
        const float* kbase = qkv + (size_t)(b * SEQ + kb * BC) * rs + DIMN + h * HDIM;
        __syncthreads();
        for (int i = tid; i < BC * (HDIM / 4); i += 256) {
            const int r = i >> 5, c4 = (i & 31) * 4;
            *(float4*)&KVs[r][c4] = *(const float4*)(kbase + (size_t)r * rs + c4);
        }
        __syncthreads();

        float s[2][2] = {{0, 0}, {0, 0}};
#pragma unroll 8
        for (int k = 0; k < HDIM; k += 4) {
            float4 q0 = *(const float4*)&Qs[tr * 2][k];
            float4 q1 = *(const float4*)&Qs[tr * 2 + 1][k];
            float4 k0 = *(const float4*)&KVs[tc * 2][k];
            float4 k1 = *(const float4*)&KVs[tc * 2 + 1][k];
            s[0][0] += q0.x * k0.x + q0.y * k0.y + q0.z * k0.z + q0.w * k0.w;
            s[0][1] += q0.x * k1.x + q0.y * k1.y + q0.z * k1.z + q0.w * k1.w;
            s[1][0] += q1.x * k0.x + q1.y * k0.y + q1.z * k0.z + q1.w * k0.w;
            s[1][1] += q1.x * k1.x + q1.y * k1.y + q1.z * k1.z + q1.w * k1.w;
        }

#pragma unroll
        for (int i = 0; i < 2; ++i) {
            float rm = fmaxf(s[i][0], s[i][1]);
#pragma unroll
            for (int off = 8; off; off >>= 1)
                rm = fmaxf(rm, __shfl_xor_sync(0xffffffffu, rm, off));
            const float nm = fmaxf(m_i[i], rm);
            const float al = __expf(m_i[i] - nm);
            m_i[i] = nm;
            const float p0 = __expf(s[i][0] - nm);
            const float p1 = __expf(s[i][1] - nm);
            Ps[tr * 2 + i][tc * 2]     = p0;
            Ps[tr * 2 + i][tc * 2 + 1] = p1;
            float rsum = p0 + p1;
#pragma unroll
            for (int off = 8; off; off >>= 1)
                rsum += __shfl_xor_sync(0xffffffffu, rsum, off);
            l_i[i] = l_i[i] * al + rsum;
#pragma unroll
            for (int c = 0; c < 8; ++c) o[i][c] *= al;
        }
        __syncthreads();

        const float* vbase = qkv + (size_t)(b * SEQ + kb * BC) * rs + 2 * DIMN + h * HDIM;
        for (int i = tid; i < BC * (HDIM / 4); i += 256) {
            const int r = i >> 5, c4 = (i & 31) * 4;
            *(float4*)&KVs[r][c4] = *(const float4*)(vbase + (size_t)r * rs + c4);
        }
        __syncthreads();

#pragma unroll 4
        for (int j = 0; j < BC; ++j) {
            float4 v0 = *(const float4*)&KVs[j][tc * 8];
            float4 v1 = *(const float4*)&KVs[j][tc * 8 + 4];
            const float p0 = Ps[tr * 2][j];
            const float p1 = Ps[tr * 2 + 1][j];
            o[0][0] = fmaf(p0, v0.x, o[0][0]); o[0][1] = fmaf(p0, v0.y, o[0][1]);
            o[0][2] = fmaf(p0, v0.z, o[0][2]); o[0][3] = fmaf(p0, v0.w, o[0][3]);
            o[0][4] = fmaf(p0, v1.x, o[0][4]); o[0][5] = fmaf(p0, v1.y, o[0][5]);
            o[0][6] = fmaf(p0, v1.z, o[0][6]); o[0][7] = fmaf(p0, v1.w, o[0][7]);
            o[1][0] = fmaf(p1, v0.x, o[1][0]); o[1][1] = fmaf(p1, v0.y, o[1][1]);
            o[1][2] = fmaf(p1, v0.z, o[1][2]); o[1][3] = fmaf(p1, v0.w, o[1][3]);
            o[1][4] = fmaf(p1, v1.x, o[1][4]); o[1][5] = fmaf(p1, v1.y, o[1][5]);
            o[1][6] = fmaf(p1, v1.z, o[1][6]); o[1][7] = fmaf(p1, v1.w, o[1][7]);
        }
    }

#pragma unroll
    for (int i = 0; i < 2; ++i) {
        const float inv = 1.0f / l_i[i];
        const int row = b * SEQ + qb * BR + tr * 2 + i;
        const size_t base = (size_t)row * DIMN + h * HDIM + tc * 8;
        uint32_t H[4], L[4];
#pragma unroll
        for (int c4 = 0; c4 < 4; ++c4) {
            float f0 = o[i][c4 * 2] * inv;
            float f1 = o[i][c4 * 2 + 1] * inv;
            __nv_bfloat16 h0 = __float2bfloat16_rn(f0);
            __nv_bfloat16 h1 = __float2bfloat16_rn(f1);
            __nv_bfloat16 l0 = __float2bfloat16_rn(f0 - __bfloat162float(h0));
            __nv_bfloat16 l1 = __float2bfloat16_rn(f1 - __bfloat162float(h1));
            H[c4] = ((uint32_t)__bfloat16_as_ushort(h1) << 16) | __bfloat16_as_ushort(h0);
            L[c4] = ((uint32_t)__bfloat16_as_ushort(l1) << 16) | __bfloat16_as_ushort(l0);
        }
        *(uint4*)(ohi + base) = *(uint4*)H;
        *(uint4*)(olo + base) = *(uint4*)L;
    }
}

// ---------------------------------------------------------------------------
// Host side
// ---------------------------------------------------------------------------
typedef CUresult (CUDAAPI *EncodeTiledFn)(
    CUtensorMap*, CUtensorMapDataType, cuuint32_t, void*,
    const cuuint64_t*, const cuuint64_t*, const cuuint32_t*, const cuuint32_t*,
    CUtensorMapInterleave, CUtensorMapSwizzle, CUtensorMapL2promotion,
    CUtensorMapFloatOOBfill);

static void make_map_bf16(EncodeTiledFn enc, CUtensorMap* m, const void* p,
                          unsigned long long d0, unsigned long long d1,
                          unsigned b0, unsigned b1)
{
    cuuint64_t dims[2]    = {d0, d1};
    cuuint64_t strides[1] = {d0 * 2};
    cuuint32_t box[2]     = {b0, b1};
    cuuint32_t es[2]      = {1, 1};
    enc(m, CU_TENSOR_MAP_DATA_TYPE_BFLOAT16, 2, (void*)p, dims, strides, box, es,
        CU_TENSOR_MAP_INTERLEAVE_NONE, CU_TENSOR_MAP_SWIZZLE_128B,
        CU_TENSOR_MAP_L2_PROMOTION_L2_128B, CU_TENSOR_MAP_FLOAT_OOB_FILL_NONE);
}

extern "C" void kernel_launch(void* const* d_in, const int* in_sizes, int n_in,
                              void* d_out, int out_size)
{
    const float* X    = (const float*)d_in[0];
    const float* fcos = (const float*)d_in[1];
    const float* fsin = (const float*)d_in[2];
    const float* Wqkv = (const float*)d_in[3];
    const float* bqkv = (const float*)d_in[4];
    const float* gq   = (const float*)d_in[5];
    const float* gk   = (const float*)d_in[6];
    const float* Wout = (const float*)d_in[7];
    const float* bout = (const float*)d_in[8];
    float* out = (float*)d_out;

    float *qkvbuf;
    __nv_bfloat16 *xhi, *xlo, *ahi, *alo, *wqhi, *wqlo, *wohi, *wolo;
    cudaGetSymbolAddress((void**)&qkvbuf, g_qkv);
    cudaGetSymbolAddress((void**)&xhi, g_xhi);
    cudaGetSymbolAddress((void**)&xlo, g_xlo);
    cudaGetSymbolAddress((void**)&ahi, g_ahi);
    cudaGetSymbolAddress((void**)&alo, g_alo);
    cudaGetSymbolAddress((void**)&wqhi, g_wqhi);
    cudaGetSymbolAddress((void**)&wqlo, g_wqlo);
    cudaGetSymbolAddress((void**)&wohi, g_wohi);
    cudaGetSymbolAddress((void**)&wolo, g_wolo);

    EncodeTiledFn enc = nullptr;
    cudaDriverEntryPointQueryResult qr;
    cudaGetDriverEntryPoint("cuTensorMapEncodeTiled", (void**)&enc,
                            cudaEnableDefault, &qr);

    CUtensorMap tXh, tXl, tWqh, tWql, tAh, tAl, tWoh, tWol;
    make_map_bf16(enc, &tXh,  xhi,  DIMN, TOKENS,   GBK, GBM);
    make_map_bf16(enc, &tXl,  xlo,  DIMN, TOKENS,   GBK, GBM);
    make_map_bf16(enc, &tWqh, wqhi, DIMN, QKV_COLS, GBK, GBN);
    make_map_bf16(enc, &tWql, wqlo, DIMN, QKV_COLS, GBK, GBN);
    make_map_bf16(enc, &tAh,  ahi,  DIMN, TOKENS,   GBK, GBM);
    make_map_bf16(enc, &tAl,  alo,  DIMN, TOKENS,   GBK, GBM);
    make_map_bf16(enc, &tWoh, wohi, DIMN, DIMN,     GBK, GBN);
    make_map_bf16(enc, &tWol, wolo, DIMN, DIMN,     GBK, GBN);

    cudaFuncSetAttribute(gemm_tma, cudaFuncAttributeMaxDynamicSharedMemorySize, GSMEM);

    // 0) precision-split operands
    split_bf16<<<(TOKENS * DIMN / 4 + 255) / 256, 256>>>(
        (const float4*)X, (uint2*)xhi, (uint2*)xlo, TOKENS * DIMN / 4);
    transpose_split<<<dim3(QKV_COLS / 32, DIMN / 32), dim3(32, 8)>>>(
        Wqkv, wqhi, wqlo, DIMN, QKV_COLS);
    transpose_split<<<dim3(DIMN / 32, DIMN / 32), dim3(32, 8)>>>(
        Wout, wohi, wolo, DIMN, DIMN);

    // 1) qkv = X @ W_qkv + b_qkv
    gemm_tma<<<dim3(TOKENS / GBM, QKV_COLS / GBN), 256, GSMEM>>>(
        tXh, tXl, tWqh, tWql, bqkv, qkvbuf, QKV_COLS);

    // 2) RMSNorm + RoPE in place
    rms_rope<<<TOKENS, 256>>>(qkvbuf, gq, gk, fcos, fsin);

    // 3) flash attention -> bf16 hi/lo planes
    flash_attn<<<dim3(SEQ / BR, BATCH * NHEADS), 256>>>(qkvbuf, ahi, alo);

    // 4) out = attn @ W_out + b_out
    gemm_tma<<<dim3(TOKENS / GBM, DIMN / GBN), 256, GSMEM>>>(
        tAh, tAl, tWoh, tWol, bout, out, DIMN);
}

// round 6
// speedup vs baseline: 1.9425x; 1.9425x over previous
#include <cuda_runtime.h>
#include <cuda_bf16.h>
#include <math.h>
#include <stdint.h>

// Problem constants
#define DIMN     5120
#define NHEADS   40
#define HDIM     128
#define BATCH    2
#define SEQ      1024
#define TOKENS   (BATCH * SEQ)        // 2048
#define QKV_COLS (3 * DIMN)           // 15360
#define EPSV     1e-6f
#define SCALEV   0.08838834764831845f // 128^-0.5

// GEMM tiling (R4 known-good): CTA 128x256, 8 warps of 64x64, BK=32, 3 stages
#define GBM 128
#define GBN 256
#define GBK 32
#define GSTAGES 3
#define AROW 40                               // (32+8) bf16 per row
#define A_PLANE (GBM * AROW * 2)              // 10240 B
#define B_PLANE (GBN * AROW * 2)              // 20480 B
#define STAGE_B (2 * A_PLANE + 2 * B_PLANE)   // 61440
#define GSMEM (GSTAGES * STAGE_B)             // 184320
#define NCHUNK (DIMN / GBK)                   // 160

// Flash tiling: Br=128 (8 warps x m16), Bc=64, D=128, 2-stage cp.async K/V
#define FBR 128
#define FBC 64
#define FROWB 272                             // 128 bf16 * 2B + 16B pad
#define FQPL (FBR * FROWB)                    // 34816
#define FKPL (FBC * FROWB)                    // 17408
#define FSTG (4 * FKPL)                       // 69632 (khi,klo,vhi,vlo)
#define FSMEM (2 * FQPL + 2 * FSTG)           // 208896

// Scratch (no allocations allowed)
__device__ float          g_qkv[(size_t)TOKENS * QKV_COLS];
__device__ __nv_bfloat16  g_xhi[(size_t)TOKENS * DIMN];
__device__ __nv_bfloat16  g_xlo[(size_t)TOKENS * DIMN];
__device__ __nv_bfloat16  g_ahi[(size_t)TOKENS * DIMN];
__device__ __nv_bfloat16  g_alo[(size_t)TOKENS * DIMN];
__device__ __nv_bfloat16  g_wqhi[(size_t)QKV_COLS * DIMN];
__device__ __nv_bfloat16  g_wqlo[(size_t)QKV_COLS * DIMN];
__device__ __nv_bfloat16  g_wohi[(size_t)DIMN * DIMN];
__device__ __nv_bfloat16  g_wolo[(size_t)DIMN * DIMN];
__device__ __nv_bfloat16  g_qh[(size_t)TOKENS * DIMN];
__device__ __nv_bfloat16  g_ql[(size_t)TOKENS * DIMN];
__device__ __nv_bfloat16  g_kh[(size_t)TOKENS * DIMN];
__device__ __nv_bfloat16  g_kl[(size_t)TOKENS * DIMN];
__device__ __nv_bfloat16  g_vh[(size_t)TOKENS * DIMN];
__device__ __nv_bfloat16  g_vl[(size_t)TOKENS * DIMN];

// ---------------------------------------------------------------------------
__device__ __forceinline__ uint32_t smem_u32(const void* p) {
    uint32_t a;
    asm("{ .reg .u64 t; cvta.to.shared.u64 t, %1; cvt.u32.u64 %0, t; }" : "=r"(a) : "l"(p));
    return a;
}
__device__ __forceinline__ void cp16(uint32_t s, const void* g) {
    asm volatile("cp.async.cg.shared.global [%0], [%1], 16;" :: "r"(s), "l"(g));
}
__device__ __forceinline__ void cp_commit() {
    asm volatile("cp.async.commit_group;" ::: "memory");
}
__device__ __forceinline__ void cp_wait1() {
    asm volatile("cp.async.wait_group 1;" ::: "memory");
}
__device__ __forceinline__ void mma_bf16(float* c, const uint32_t* a, const uint32_t* b) {
    asm volatile("mma.sync.aligned.m16n8k16.row.col.f32.bf16.bf16.f32 "
        "{%0,%1,%2,%3}, {%4,%5,%6,%7}, {%8,%9}, {%0,%1,%2,%3};"
        : "+f"(c[0]), "+f"(c[1]), "+f"(c[2]), "+f"(c[3])
        : "r"(a[0]), "r"(a[1]), "r"(a[2]), "r"(a[3]), "r"(b[0]), "r"(b[1]));
}
__device__ __forceinline__ void ldsm_x4(uint32_t* r, uint32_t a) {
    asm volatile("ldmatrix.sync.aligned.m8n8.x4.shared.b16 {%0,%1,%2,%3}, [%4];"
        : "=r"(r[0]), "=r"(r[1]), "=r"(r[2]), "=r"(r[3]) : "r"(a));
}
__device__ __forceinline__ void ldsm_x2(uint32_t* r, uint32_t a) {
    asm volatile("ldmatrix.sync.aligned.m8n8.x2.shared.b16 {%0,%1}, [%2];"
        : "=r"(r[0]), "=r"(r[1]) : "r"(a));
}
__device__ __forceinline__ void ldsm_x2t(uint32_t* r, uint32_t a) {
    asm volatile("ldmatrix.sync.aligned.m8n8.x2.trans.shared.b16 {%0,%1}, [%2];"
        : "=r"(r[0]), "=r"(r[1]) : "r"(a));
}
__device__ __forceinline__ void bsplit2(float x, float y, uint32_t& hi, uint32_t& lo) {
    __nv_bfloat16 hx = __float2bfloat16_rn(x), hy = __float2bfloat16_rn(y);
    __nv_bfloat16 lx = __float2bfloat16_rn(x - __bfloat162float(hx));
    __nv_bfloat16 ly = __float2bfloat16_rn(y - __bfloat162float(hy));
    hi = ((uint32_t)__bfloat16_as_ushort(hy) << 16) | __bfloat16_as_ushort(hx);
    lo = ((uint32_t)__bfloat16_as_ushort(ly) << 16) | __bfloat16_as_ushort(lx);
}

// ---------------------------------------------------------------------------
// GEMM (R4): C[M, Ntot] = A @ B^T + bias, 3-pass split bf16 (hh + hl + lh).
// ---------------------------------------------------------------------------
__global__ __launch_bounds__(256, 1) void gemm_bf16x3(
    const __nv_bfloat16* __restrict__ Ahi, const __nv_bfloat16* __restrict__ Alo,
    const __nv_bfloat16* __restrict__ Bhi, const __nv_bfloat16* __restrict__ Blo,
    const float* __restrict__ bias, float* __restrict__ C, int Ntot)
{
    extern __shared__ char gsm[];
    const uint32_t sbase = smem_u32(gsm);
    const int tid = threadIdx.x;
    const int m0  = blockIdx.x * GBM;
    const int n0  = blockIdx.y * GBN;
    const int K   = DIMN;

    const int wid  = tid >> 5, lane = tid & 31;
    const int wm   = wid & 1;
    const int wn   = wid >> 1;
    const int gid  = lane >> 2;
    const int tig  = lane & 3;
    const int AROWB = AROW * 2;

    float acc[4][8][4];
#pragma unroll
    for (int a = 0; a < 4; ++a)
#pragma unroll
        for (int b = 0; b < 8; ++b)
#pragma unroll
            for (int c = 0; c < 4; ++c) acc[a][b][c] = 0.0f;

    auto issue = [&](int s, int k0) {
        const uint32_t st = sbase + s * STAGE_B;
#pragma unroll
        for (int i = 0; i < 4; ++i) {
            const int idx = tid + 256 * i;
            const int p   = idx >> 9;
            const int r   = (idx >> 2) & 127;
            const int ch  = idx & 3;
            const __nv_bfloat16* src = (p ? Alo : Ahi) + (size_t)(m0 + r) * K + k0 + ch * 8;
            cp16(st + p * A_PLANE + r * AROWB + ch * 16, src);
        }
#pragma unroll
        for (int i = 0; i < 8; ++i) {
            const int idx = tid + 256 * i;
            const int p   = idx >> 10;
            const int r   = (idx >> 2) & 255;
            const int ch  = idx & 3;
            const __nv_bfloat16* src = (p ? Blo : Bhi) + (size_t)(n0 + r) * K + k0 + ch * 8;
            cp16(st + 2 * A_PLANE + p * B_PLANE + r * AROWB + ch * 16, src);
        }
        cp_commit();
    };

    issue(0, 0);
    issue(1, GBK);

    for (int it = 0; it < NCHUNK; ++it) {
        cp_wait1();
        __syncthreads();
        const int nxt = it + 2;
        if (nxt < NCHUNK) issue(nxt % GSTAGES, nxt * GBK);

        const char* st = gsm + (it % GSTAGES) * STAGE_B;
#pragma unroll
        for (int ks = 0; ks < 2; ++ks) {
            const int cofs = (ks * 16 + tig * 2) * 2;
            uint32_t ah[4][4], al[4][4];
#pragma unroll
            for (int mt = 0; mt < 4; ++mt) {
                const char* p = st + (wm * 64 + mt * 16 + gid) * AROWB + cofs;
                ah[mt][0] = *(const uint32_t*)(p);
                ah[mt][1] = *(const uint32_t*)(p + 8 * AROWB);
                ah[mt][2] = *(const uint32_t*)(p + 16);
                ah[mt][3] = *(const uint32_t*)(p + 8 * AROWB + 16);
                const char* q = p + A_PLANE;
                al[mt][0] = *(const uint32_t*)(q);
                al[mt][1] = *(const uint32_t*)(q + 8 * AROWB);
                al[mt][2] = *(const uint32_t*)(q + 16);
                al[mt][3] = *(const uint32_t*)(q + 8 * AROWB + 16);
            }
            uint32_t bh[8][2], bl[8][2];
#pragma unroll
            for (int nt = 0; nt < 8; ++nt) {
                const char* p = st + 2 * A_PLANE + (wn * 64 + nt * 8 + gid) * AROWB + cofs;
                bh[nt][0] = *(const uint32_t*)(p);
                bh[nt][1] = *(const uint32_t*)(p + 16);
                const char* q = p + B_PLANE;
                bl[nt][0] = *(const uint32_t*)(q);
                bl[nt][1] = *(const uint32_t*)(q + 16);
            }
#pragma unroll
            for (int mt = 0; mt < 4; ++mt)
#pragma unroll
                for (int nt = 0; nt < 8; ++nt)
                    mma_bf16(acc[mt][nt], ah[mt], bh[nt]);
#pragma unroll
            for (int mt = 0; mt < 4; ++mt)
#pragma unroll
                for (int nt = 0; nt < 8; ++nt)
                    mma_bf16(acc[mt][nt], ah[mt], bl[nt]);
#pragma unroll
            for (int mt = 0; mt < 4; ++mt)
#pragma unroll
                for (int nt = 0; nt < 8; ++nt)
                    mma_bf16(acc[mt][nt], al[mt], bh[nt]);
        }
        __syncthreads();
    }

#pragma unroll
    for (int mt = 0; mt < 4; ++mt) {
#pragma unroll
        for (int nt = 0; nt < 8; ++nt) {
            const int row = m0 + wm * 64 + mt * 16 + gid;
            const int col = n0 + wn * 64 + nt * 8 + tig * 2;
            const float b0 = bias[col], b1 = bias[col + 1];
            float2 v0 = {acc[mt][nt][0] + b0, acc[mt][nt][1] + b1};
            float2 v1 = {acc[mt][nt][2] + b0, acc[mt][nt][3] + b1};
            *(float2*)(C + (size_t)row * Ntot + col)       = v0;
            *(float2*)(C + (size_t)(row + 8) * Ntot + col) = v1;
        }
    }
}

// ---------------------------------------------------------------------------
__global__ __launch_bounds__(256) void split_bf16(
    const float4* __restrict__ in, uint2* __restrict__ hi, uint2* __restrict__ lo, int n4)
{
    const int i = blockIdx.x * 256 + threadIdx.x;
    if (i >= n4) return;
    float4 v = in[i];
    uint32_t H0, L0, H1, L1;
    bsplit2(v.x, v.y, H0, L0);
    bsplit2(v.z, v.w, H1, L1);
    hi[i] = make_uint2(H0, H1);
    lo[i] = make_uint2(L0, L1);
}

__global__ __launch_bounds__(256) void transpose_split(
    const float* __restrict__ W,
    __nv_bfloat16* __restrict__ Whi, __nv_bfloat16* __restrict__ Wlo, int K, int N)
{
    __shared__ float t[32][33];
    const int n0 = blockIdx.x * 32, k0 = blockIdx.y * 32;
    const int tx = threadIdx.x, ty = threadIdx.y;
#pragma unroll
    for (int i = 0; i < 32; i += 8)
        t[ty + i][tx] = W[(size_t)(k0 + ty + i) * N + n0 + tx];
    __syncthreads();
#pragma unroll
    for (int i = 0; i < 32; i += 8) {
        float x = t[tx][ty + i];
        __nv_bfloat16 h = __float2bfloat16_rn(x);
        __nv_bfloat16 l = __float2bfloat16_rn(x - __bfloat162float(h));
        const size_t idx = (size_t)(n0 + ty + i) * K + k0 + tx;
        Whi[idx] = h;
        Wlo[idx] = l;
    }
}

// ---------------------------------------------------------------------------
// RMSNorm + rotary; emits split-bf16 q (pre-scaled), k, and v planes.
// ---------------------------------------------------------------------------
__global__ __launch_bounds__(256) void rms_rope_split(
    const float* __restrict__ qkv,
    const float* __restrict__ gq, const float* __restrict__ gk,
    const float* __restrict__ fcos, const float* __restrict__ fsin,
    __nv_bfloat16* __restrict__ qh, __nv_bfloat16* __restrict__ ql,
    __nv_bfloat16* __restrict__ kh, __nv_bfloat16* __restrict__ kl,
    __nv_bfloat16* __restrict__ vh, __nv_bfloat16* __restrict__ vl)
{
    const int t   = blockIdx.x;
    const int l   = t & (SEQ - 1);
    const int tid = threadIdx.x;

    const float* qrow = qkv + (size_t)t * QKV_COLS;
    const float* krow = qrow + DIMN;
    const float* vrow = qrow + 2 * DIMN;

    float sq = 0.0f, sk = 0.0f;
    for (int i = tid; i < DIMN; i += 256) {
        float a = qrow[i]; sq = fmaf(a, a, sq);
        float b = krow[i]; sk = fmaf(b, b, sk);
    }
#pragma unroll
    for (int off = 16; off; off >>= 1) {
        sq += __shfl_xor_sync(0xffffffffu, sq, off);
        sk += __shfl_xor_sync(0xffffffffu, sk, off);
    }
    __shared__ float redq[8], redk[8];
    __shared__ float bq, bk;
    const int warp = tid >> 5, lane = tid & 31;
    if (lane == 0) { redq[warp] = sq; redk[warp] = sk; }
    __syncthreads();
    if (tid == 0) {
        float a = 0.0f, b = 0.0f;
#pragma unroll
        for (int w = 0; w < 8; ++w) { a += redq[w]; b += redk[w]; }
        bq = a; bk = b;
    }
    __syncthreads();
    const float rq = rsqrtf(bq * (1.0f / DIMN) + EPSV);
    const float rk = rsqrtf(bk * (1.0f / DIMN) + EPSV);

    const size_t ob = (size_t)t * DIMN;
    for (int p = tid; p < DIMN / 2; p += 256) {
        const int head = p >> 6;
        const int i2   = (p & 63) * 2;
        const int ce   = head * HDIM + i2;
        const int co   = ce + 1;
        const float ccos = fcos[l * HDIM + i2];
        const float csin = fsin[l * HDIM + i2 + 1];

        float xe = qrow[ce] * rq * gq[ce];
        float xo = qrow[co] * rq * gq[co];
        float qe = (xe * ccos - xo * csin) * SCALEV;
        float qo = (xe * csin + xo * ccos) * SCALEV;
        uint32_t H, L;
        bsplit2(qe, qo, H, L);
        *(uint32_t*)(qh + ob + ce) = H;
        *(uint32_t*)(ql + ob + ce) = L;

        xe = krow[ce] * rk * gk[ce];
        xo = krow[co] * rk * gk[co];
        float ke = xe * ccos - xo * csin;
        float ko = xe * csin + xo * ccos;
        bsplit2(ke, ko, H, L);
        *(uint32_t*)(kh + ob + ce) = H;
        *(uint32_t*)(kl + ob + ce) = L;

        float v0 = vrow[ce], v1 = vrow[co];
        bsplit2(v0, v1, H, L);
        *(uint32_t*)(vh + ob + ce) = H;
        *(uint32_t*)(vl + ob + ce) = L;
    }
}

// ---------------------------------------------------------------------------
// Tensor-core flash attention. Br=128, Bc=64, D=128.
// S = 3-pass split (qh*kh + qh*kl + ql*kh); PV = 3-pass (ph*vh + ph*vl + pl*vh).
// Output: split-bf16 planes for GEMM2.
// ---------------------------------------------------------------------------
__global__ __launch_bounds__(256, 1) void flash_mma(
    const __nv_bfloat16* __restrict__ qhp, const __nv_bfloat16* __restrict__ qlp,
    const __nv_bfloat16* __restrict__ khp, const __nv_bfloat16* __restrict__ klp,
    const __nv_bfloat16* __restrict__ vhp, const __nv_bfloat16* __restrict__ vlp,
    __nv_bfloat16* __restrict__ ohi, __nv_bfloat16* __restrict__ olo)
{
    extern __shared__ char fsm[];
    const uint32_t sb = smem_u32(fsm);

    const int qb = blockIdx.x, bh = blockIdx.y;
    const int b  = bh / NHEADS, h = bh % NHEADS;
    const int tid = threadIdx.x, wid = tid >> 5, lane = tid & 31;
    const int gid = lane >> 2, tig = lane & 3;
    const int l15 = lane & 15;
    const int hofs = h * HDIM;
    const size_t qrow0 = (size_t)(b * SEQ + qb * FBR);
    const size_t krow0 = (size_t)(b * SEQ);

    // Q load (both planes), part of cp.async group 0
    for (int i = 0; i < 16; ++i) {
        const int idx = tid + 256 * i;        // 0..4095
        const int pl  = idx >> 11;
        const int r   = (idx >> 4) & 127;
        const int c   = idx & 15;
        const __nv_bfloat16* src = (pl ? qlp : qhp) + (qrow0 + r) * DIMN + hofs + c * 8;
        cp16(sb + pl * FQPL + r * FROWB + c * 16, src);
    }
    auto loadkv = [&](int s, int kb) {
        const uint32_t st = sb + 2 * FQPL + s * FSTG;
        const size_t kr = krow0 + (size_t)kb * FBC;
        for (int i = 0; i < 16; ++i) {
            const int idx = tid + 256 * i;    // 0..4095
            const int pl  = idx >> 10;        // 0..3
            const int r   = (idx >> 4) & 63;
            const int c   = idx & 15;
            const __nv_bfloat16* base = (pl == 0) ? khp : (pl == 1) ? klp
                                      : (pl == 2) ? vhp : vlp;
            cp16(st + pl * FKPL + r * FROWB + c * 16, base + (kr + r) * DIMN + hofs + c * 8);
        }
        cp_commit();
    };
    loadkv(0, 0);
    loadkv(1, 1);

    float oacc[16][4];
#pragma unroll
    for (int d = 0; d < 16; ++d)
#pragma unroll
        for (int c = 0; c < 4; ++c) oacc[d][c] = 0.0f;
    float mrow[2] = {-1e30f, -1e30f};
    float lrow[2] = {0.0f, 0.0f};

    const int qrow = wid * 16 + l15;
    const uint32_t qcol = ((lane >> 4) & 1) * 16;
    const int krw  = l15 & 7;
    const uint32_t kcadd = ((l15 >> 3) & 1) * 16;

    for (int kb = 0; kb < SEQ / FBC; ++kb) {
        cp_wait1();
        __syncthreads();
        const uint32_t st = sb + 2 * FQPL + (kb & 1) * FSTG;
        const uint32_t kh = st, kl = st + FKPL, vh = st + 2 * FKPL, vl = st + 3 * FKPL;

        // ---- S = Q K^T (split 3-pass) ----
        float sacc[8][4];
#pragma unroll
        for (int nt = 0; nt < 8; ++nt)
#pragma unroll
            for (int c = 0; c < 4; ++c) sacc[nt][c] = 0.0f;

#pragma unroll
        for (int kc = 0; kc < 8; ++kc) {
            uint32_t aqh[4], aql[4];
            ldsm_x4(aqh, sb + qrow * FROWB + kc * 32 + qcol);
            ldsm_x4(aql, sb + FQPL + qrow * FROWB + kc * 32 + qcol);
            const uint32_t kcol = kc * 32 + kcadd;
#pragma unroll
            for (int nt = 0; nt < 8; ++nt) {
                uint32_t bkh[2], bkl[2];
                ldsm_x2(bkh, kh + (nt * 8 + krw) * FROWB + kcol);
                ldsm_x2(bkl, kl + (nt * 8 + krw) * FROWB + kcol);
                mma_bf16(sacc[nt], aqh, bkh);
                mma_bf16(sacc[nt], aqh, bkl);
                mma_bf16(sacc[nt], aql, bkh);
            }
        }

        // ---- online softmax ----
        float mx0 = sacc[0][0], mx1 = sacc[0][2];
#pragma unroll
        for (int nt = 0; nt < 8; ++nt) {
            mx0 = fmaxf(mx0, fmaxf(sacc[nt][0], sacc[nt][1]));
            mx1 = fmaxf(mx1, fmaxf(sacc[nt][2], sacc[nt][3]));
        }
        mx0 = fmaxf(mx0, __shfl_xor_sync(0xffffffffu, mx0, 1));
        mx0 = fmaxf(mx0, __shfl_xor_sync(0xffffffffu, mx0, 2));
        mx1 = fmaxf(mx1, __shfl_xor_sync(0xffffffffu, mx1, 1));
        mx1 = fmaxf(mx1, __shfl_xor_sync(0xffffffffu, mx1, 2));
        const float mn0 = fmaxf(mrow[0], mx0);
        const float mn1 = fmaxf(mrow[1], mx1);
        const float al0 = __expf(mrow[0] - mn0);
        const float al1 = __expf(mrow[1] - mn1);
        mrow[0] = mn0; mrow[1] = mn1;

        float rs0 = 0.0f, rs1 = 0.0f;
#pragma unroll
        for (int nt = 0; nt < 8; ++nt) {
            sacc[nt][0] = __expf(sacc[nt][0] - mn0);
            sacc[nt][1] = __expf(sacc[nt][1] - mn0);
            sacc[nt][2] = __expf(sacc[nt][2] - mn1);
            sacc[nt][3] = __expf(sacc[nt][3] - mn1);
            rs0 += sacc[nt][0] + sacc[nt][1];
            rs1 += sacc[nt][2] + sacc[nt][3];
        }
        rs0 += __shfl_xor_sync(0xffffffffu, rs0, 1);
        rs0 += __shfl_xor_sync(0xffffffffu, rs0, 2);
        rs1 += __shfl_xor_sync(0xffffffffu, rs1, 1);
        rs1 += __shfl_xor_sync(0xffffffffu, rs1, 2);
        lrow[0] = lrow[0] * al0 + rs0;
        lrow[1] = lrow[1] * al1 + rs1;
#pragma unroll
        for (int d = 0; d < 16; ++d) {
            oacc[d][0] *= al0; oacc[d][1] *= al0;
            oacc[d][2] *= al1; oacc[d][3] *= al1;
        }

        // ---- O += P V (split 3-pass) ----
#pragma unroll
        for (int kc2 = 0; kc2 < 4; ++kc2) {
            uint32_t aph[4], apl[4];
            bsplit2(sacc[2 * kc2][0],     sacc[2 * kc2][1],     aph[0], apl[0]);
            bsplit2(sacc[2 * kc2][2],     sacc[2 * kc2][3],     aph[1], apl[1]);
            bsplit2(sacc[2 * kc2 + 1][0], sacc[2 * kc2 + 1][1], aph[2], apl[2]);
            bsplit2(sacc[2 * kc2 + 1][2], sacc[2 * kc2 + 1][3], aph[3], apl[3]);
            const uint32_t vr = (kc2 * 16 + l15) * FROWB;
#pragma unroll
            for (int dt = 0; dt < 16; ++dt) {
                uint32_t bvh[2], bvl[2];
                ldsm_x2t(bvh, vh + vr + dt * 16);
                ldsm_x2t(bvl, vl + vr + dt * 16);
                mma_bf16(oacc[dt], aph, bvh);
                mma_bf16(oacc[dt], aph, bvl);
                mma_bf16(oacc[dt], apl, bvh);
            }
        }
        __syncthreads();
        if (kb + 2 < SEQ / FBC) loadkv(kb & 1, kb + 2);
    }

    // ---- epilogue: normalize, split-bf16 store ----
#pragma unroll
    for (int i = 0; i < 2; ++i) {
        const float inv = 1.0f / lrow[i];
        const size_t base =
            (qrow0 + (size_t)(wid * 16 + gid + i * 8)) * DIMN + hofs + tig * 2;
#pragma unroll
        for (int dt = 0; dt < 16; ++dt) {
            uint32_t H, L;
            bsplit2(oacc[dt][2 * i] * inv, oacc[dt][2 * i + 1] * inv, H, L);
            *(uint32_t*)(ohi + base + dt * 8) = H;
            *(uint32_t*)(olo + base + dt * 8) = L;
        }
    }
}

// ---------------------------------------------------------------------------
extern "C" void kernel_launch(void* const* d_in, const int* in_sizes, int n_in,
                              void* d_out, int out_size)
{
    const float* X    = (const float*)d_in[0];
    const float* fcos = (const float*)d_in[1];
    const float* fsin = (const float*)d_in[2];
    const float* Wqkv = (const float*)d_in[3];
    const float* bqkv = (const float*)d_in[4];
    const float* gq   = (const float*)d_in[5];
    const float* gk   = (const float*)d_in[6];
    const float* Wout = (const float*)d_in[7];
    const float* bout = (const float*)d_in[8];
    float* out = (float*)d_out;

    float *qkvbuf;
    __nv_bfloat16 *xhi, *xlo, *ahi, *alo, *wqhi, *wqlo, *wohi, *wolo;
    __nv_bfloat16 *qh, *ql, *kh, *kl, *vh, *vl;
    cudaGetSymbolAddress((void**)&qkvbuf, g_qkv);
    cudaGetSymbolAddress((void**)&xhi, g_xhi);
    cudaGetSymbolAddress((void**)&xlo, g_xlo);
    cudaGetSymbolAddress((void**)&ahi, g_ahi);
    cudaGetSymbolAddress((void**)&alo, g_alo);
    cudaGetSymbolAddress((void**)&wqhi, g_wqhi);
    cudaGetSymbolAddress((void**)&wqlo, g_wqlo);
    cudaGetSymbolAddress((void**)&wohi, g_wohi);
    cudaGetSymbolAddress((void**)&wolo, g_wolo);
    cudaGetSymbolAddress((void**)&qh, g_qh);
    cudaGetSymbolAddress((void**)&ql, g_ql);
    cudaGetSymbolAddress((void**)&kh, g_kh);
    cudaGetSymbolAddress((void**)&kl, g_kl);
    cudaGetSymbolAddress((void**)&vh, g_vh);
    cudaGetSymbolAddress((void**)&vl, g_vl);

    cudaFuncSetAttribute(gemm_bf16x3, cudaFuncAttributeMaxDynamicSharedMemorySize, GSMEM);
    cudaFuncSetAttribute(flash_mma, cudaFuncAttributeMaxDynamicSharedMemorySize, FSMEM);

    // 0) precision-split operands
    split_bf16<<<(TOKENS * DIMN / 4 + 255) / 256, 256>>>(
        (const float4*)X, (uint2*)xhi, (uint2*)xlo, TOKENS * DIMN / 4);
    transpose_split<<<dim3(QKV_COLS / 32, DIMN / 32), dim3(32, 8)>>>(
        Wqkv, wqhi, wqlo, DIMN, QKV_COLS);
    transpose_split<<<dim3(DIMN / 32, DIMN / 32), dim3(32, 8)>>>(
        Wout, wohi, wolo, DIMN, DIMN);

    // 1) qkv = X @ W_qkv + b_qkv
    gemm_bf16x3<<<dim3(TOKENS / GBM, QKV_COLS / GBN), 256, GSMEM>>>(
        xhi, xlo, wqhi, wqlo, bqkv, qkvbuf, QKV_COLS);

    // 2) RMSNorm + RoPE -> split planes
    rms_rope_split<<<TOKENS, 256>>>(qkvbuf, gq, gk, fcos, fsin,
                                    qh, ql, kh, kl, vh, vl);

    // 3) tensor-core flash attention -> bf16 hi/lo planes
    flash_mma<<<dim3(SEQ / FBR, BATCH * NHEADS), 256, FSMEM>>>(
        qh, ql, kh, kl, vh, vl, ahi, alo);

    // 4) out = attn @ W_out + b_out
    gemm_bf16x3<<<dim3(TOKENS / GBM, DIMN / GBN), 256, GSMEM>>>(
        ahi, alo, wohi, wolo, bout, out, DIMN);
}

// round 8
// speedup vs baseline: 1.9705x; 1.0144x over previous
#include <cuda_runtime.h>
#include <cuda_bf16.h>
#include <math.h>
#include <stdint.h>

// Problem constants
#define DIMN     5120
#define NHEADS   40
#define HDIM     128
#define BATCH    2
#define SEQ      1024
#define TOKENS   (BATCH * SEQ)        // 2048
#define QKV_COLS (3 * DIMN)           // 15360
#define EPSV     1e-6f
#define SCALEV   0.08838834764831845f // 128^-0.5

// GEMM tiling: CTA 128x256, 8 warps of 64x64, BK=32, 3 stages
#define GBM 128
#define GBN 256
#define GBK 32
#define GSTAGES 3
#define AROW 40                               // (32+8) bf16 per row
#define AROWB (AROW * 2)                      // 80 bytes
#define A_PLANE (GBM * AROWB)                 // 10240 B
#define B_PLANE (GBN * AROWB)                 // 20480 B
#define STAGE_B (2 * A_PLANE + 2 * B_PLANE)   // 61440
#define GSMEM (GSTAGES * STAGE_B)             // 184320
#define NCHUNK (DIMN / GBK)                   // 160

// Flash tiling: Br=128 (8 warps x m16), Bc=64, D=128, 2-stage cp.async K/V
#define FBR 128
#define FBC 64
#define FROWB 272                             // 128 bf16 * 2B + 16B pad
#define FQPL (FBR * FROWB)                    // 34816
#define FKPL (FBC * FROWB)                    // 17408
#define FSTG (4 * FKPL)                       // 69632 (khi,klo,vhi,vlo)
#define FSMEM (2 * FQPL + 2 * FSTG)           // 208896

// Scratch (no allocations allowed)
__device__ float          g_qkv[(size_t)TOKENS * QKV_COLS];
__device__ __nv_bfloat16  g_xhi[(size_t)TOKENS * DIMN];
__device__ __nv_bfloat16  g_xlo[(size_t)TOKENS * DIMN];
__device__ __nv_bfloat16  g_ahi[(size_t)TOKENS * DIMN];
__device__ __nv_bfloat16  g_alo[(size_t)TOKENS * DIMN];
__device__ __nv_bfloat16  g_wqhi[(size_t)QKV_COLS * DIMN];
__device__ __nv_bfloat16  g_wqlo[(size_t)QKV_COLS * DIMN];
__device__ __nv_bfloat16  g_wohi[(size_t)DIMN * DIMN];
__device__ __nv_bfloat16  g_wolo[(size_t)DIMN * DIMN];
__device__ __nv_bfloat16  g_qh[(size_t)TOKENS * DIMN];
__device__ __nv_bfloat16  g_ql[(size_t)TOKENS * DIMN];
__device__ __nv_bfloat16  g_kh[(size_t)TOKENS * DIMN];
__device__ __nv_bfloat16  g_kl[(size_t)TOKENS * DIMN];
__device__ __nv_bfloat16  g_vh[(size_t)TOKENS * DIMN];
__device__ __nv_bfloat16  g_vl[(size_t)TOKENS * DIMN];

// ---------------------------------------------------------------------------
__device__ __forceinline__ uint32_t smem_u32(const void* p) {
    uint32_t a;
    asm("{ .reg .u64 t; cvta.to.shared.u64 t, %1; cvt.u32.u64 %0, t; }" : "=r"(a) : "l"(p));
    return a;
}
__device__ __forceinline__ void cp16(uint32_t s, const void* g) {
    asm volatile("cp.async.cg.shared.global [%0], [%1], 16;" :: "r"(s), "l"(g));
}
__device__ __forceinline__ void cp_commit() {
    asm volatile("cp.async.commit_group;" ::: "memory");
}
__device__ __forceinline__ void cp_wait1() {
    asm volatile("cp.async.wait_group 1;" ::: "memory");
}
__device__ __forceinline__ void mma_bf16(float* c, const uint32_t* a, const uint32_t* b) {
    asm volatile("mma.sync.aligned.m16n8k16.row.col.f32.bf16.bf16.f32 "
        "{%0,%1,%2,%3}, {%4,%5,%6,%7}, {%8,%9}, {%0,%1,%2,%3};"
        : "+f"(c[0]), "+f"(c[1]), "+f"(c[2]), "+f"(c[3])
        : "r"(a[0]), "r"(a[1]), "r"(a[2]), "r"(a[3]), "r"(b[0]), "r"(b[1]));
}
__device__ __forceinline__ void ldsm_x4(uint32_t* r, uint32_t a) {
    asm volatile("ldmatrix.sync.aligned.m8n8.x4.shared.b16 {%0,%1,%2,%3}, [%4];"
        : "=r"(r[0]), "=r"(r[1]), "=r"(r[2]), "=r"(r[3]) : "r"(a));
}
__device__ __forceinline__ void ldsm_x2(uint32_t* r, uint32_t a) {
    asm volatile("ldmatrix.sync.aligned.m8n8.x2.shared.b16 {%0,%1}, [%2];"
        : "=r"(r[0]), "=r"(r[1]) : "r"(a));
}
__device__ __forceinline__ void ldsm_x2t(uint32_t* r, uint32_t a) {
    asm volatile("ldmatrix.sync.aligned.m8n8.x2.trans.shared.b16 {%0,%1}, [%2];"
        : "=r"(r[0]), "=r"(r[1]) : "r"(a));
}
__device__ __forceinline__ void bsplit2(float x, float y, uint32_t& hi, uint32_t& lo) {
    __nv_bfloat16 hx = __float2bfloat16_rn(x), hy = __float2bfloat16_rn(y);
    __nv_bfloat16 lx = __float2bfloat16_rn(x - __bfloat162float(hx));
    __nv_bfloat16 ly = __float2bfloat16_rn(y - __bfloat162float(hy));
    hi = ((uint32_t)__bfloat16_as_ushort(hy) << 16) | __bfloat16_as_ushort(hx);
    lo = ((uint32_t)__bfloat16_as_ushort(ly) << 16) | __bfloat16_as_ushort(lx);
}

// ---------------------------------------------------------------------------
// GEMM: C[M, Ntot] = A @ B^T + bias, 3-pass split bf16 (hh + hl + lh).
// Fragment loads via ldmatrix (A: x4, B: x2). Row stride 80B => conflict-free.
// ---------------------------------------------------------------------------
__global__ __launch_bounds__(256, 1) void gemm_bf16x3(
    const __nv_bfloat16* __restrict__ Ahi, const __nv_bfloat16* __restrict__ Alo,
    const __nv_bfloat16* __restrict__ Bhi, const __nv_bfloat16* __restrict__ Blo,
    const float* __restrict__ bias, float* __restrict__ C, int Ntot)
{
    extern __shared__ char gsm[];
    const uint32_t sbase = smem_u32(gsm);
    const int tid = threadIdx.x;
    const int m0  = blockIdx.x * GBM;
    const int n0  = blockIdx.y * GBN;
    const int K   = DIMN;

    const int wid  = tid >> 5, lane = tid & 31;
    const int wm   = wid & 1;
    const int wn   = wid >> 1;
    const int gid  = lane >> 2;
    const int tig  = lane & 3;
    const int l15  = lane & 15;

    // ldmatrix source rows/col-halves (uniform across all 32 lanes for validity)
    const uint32_t a_row  = (uint32_t)(wm * 64 + l15);            // + mt*16
    const uint32_t a_colh = (uint32_t)((lane >> 4) << 4);         // +16B for k=8..15
    const uint32_t b_row  = (uint32_t)(wn * 64 + (lane & 7));     // + nt*8
    const uint32_t b_colh = (uint32_t)(((lane >> 3) & 1) << 4);

    float acc[4][8][4];
#pragma unroll
    for (int a = 0; a < 4; ++a)
#pragma unroll
        for (int b = 0; b < 8; ++b)
#pragma unroll
            for (int c = 0; c < 4; ++c) acc[a][b][c] = 0.0f;

    auto issue = [&](int s, int k0) {
        const uint32_t st = sbase + s * STAGE_B;
#pragma unroll
        for (int i = 0; i < 4; ++i) {
            const int idx = tid + 256 * i;
            const int p   = idx >> 9;
            const int r   = (idx >> 2) & 127;
            const int ch  = idx & 3;
            const __nv_bfloat16* src = (p ? Alo : Ahi) + (size_t)(m0 + r) * K + k0 + ch * 8;
            cp16(st + p * A_PLANE + r * AROWB + ch * 16, src);
        }
#pragma unroll
        for (int i = 0; i < 8; ++i) {
            const int idx = tid + 256 * i;
            const int p   = idx >> 10;
            const int r   = (idx >> 2) & 255;
            const int ch  = idx & 3;
            const __nv_bfloat16* src = (p ? Blo : Bhi) + (size_t)(n0 + r) * K + k0 + ch * 8;
            cp16(st + 2 * A_PLANE + p * B_PLANE + r * AROWB + ch * 16, src);
        }
        cp_commit();
    };

    issue(0, 0);
    issue(1, GBK);

    for (int it = 0; it < NCHUNK; ++it) {
        cp_wait1();
        __syncthreads();
        const int nxt = it + 2;
        if (nxt < NCHUNK) issue(nxt % GSTAGES, nxt * GBK);

        const uint32_t ss = sbase + (it % GSTAGES) * STAGE_B;
#pragma unroll
        for (int ks = 0; ks < 2; ++ks) {
            const uint32_t kofs = (uint32_t)(ks * 32);   // 16 bf16 = 32B per k-step

            uint32_t ah[4][4], al[4][4];
#pragma unroll
            for (int mt = 0; mt < 4; ++mt) {
                const uint32_t aaddr = ss + (a_row + mt * 16) * AROWB + kofs + a_colh;
                ldsm_x4(ah[mt], aaddr);
                ldsm_x4(al[mt], aaddr + A_PLANE);
            }
            uint32_t bh[8][2], bl[8][2];
#pragma unroll
            for (int nt = 0; nt < 8; ++nt) {
                const uint32_t baddr =
                    ss + 2 * A_PLANE + (b_row + nt * 8) * AROWB + kofs + b_colh;
                ldsm_x2(bh[nt], baddr);
                ldsm_x2(bl[nt], baddr + B_PLANE);
            }
            // pass-major: consecutive MMAs hit different accumulators
#pragma unroll
            for (int mt = 0; mt < 4; ++mt)
#pragma unroll
                for (int nt = 0; nt < 8; ++nt)
                    mma_bf16(acc[mt][nt], ah[mt], bh[nt]);
#pragma unroll
            for (int mt = 0; mt < 4; ++mt)
#pragma unroll
                for (int nt = 0; nt < 8; ++nt)
                    mma_bf16(acc[mt][nt], ah[mt], bl[nt]);
#pragma unroll
            for (int mt = 0; mt < 4; ++mt)
#pragma unroll
                for (int nt = 0; nt < 8; ++nt)
                    mma_bf16(acc[mt][nt], al[mt], bh[nt]);
        }
        __syncthreads();
    }

#pragma unroll
    for (int mt = 0; mt < 4; ++mt) {
#pragma unroll
        for (int nt = 0; nt < 8; ++nt) {
            const int row = m0 + wm * 64 + mt * 16 + gid;
            const int col = n0 + wn * 64 + nt * 8 + tig * 2;
            const float b0 = bias[col], b1 = bias[col + 1];
            float2 v0 = {acc[mt][nt][0] + b0, acc[mt][nt][1] + b1};
            float2 v1 = {acc[mt][nt][2] + b0, acc[mt][nt][3] + b1};
            *(float2*)(C + (size_t)row * Ntot + col)       = v0;
            *(float2*)(C + (size_t)(row + 8) * Ntot + col) = v1;
        }
    }
}

// ---------------------------------------------------------------------------
__global__ __launch_bounds__(256) void split_bf16(
    const float4* __restrict__ in, uint2* __restrict__ hi, uint2* __restrict__ lo, int n4)
{
    const int i = blockIdx.x * 256 + threadIdx.x;
    if (i >= n4) return;
    float4 v = in[i];
    uint32_t H0, L0, H1, L1;
    bsplit2(v.x, v.y, H0, L0);
    bsplit2(v.z, v.w, H1, L1);
    hi[i] = make_uint2(H0, H1);
    lo[i] = make_uint2(L0, L1);
}

__global__ __launch_bounds__(256) void transpose_split(
    const float* __restrict__ W,
    __nv_bfloat16* __restrict__ Whi, __nv_bfloat16* __restrict__ Wlo, int K, int N)
{
    __shared__ float t[32][33];
    const int n0 = blockIdx.x * 32, k0 = blockIdx.y * 32;
    const int tx = threadIdx.x, ty = threadIdx.y;
#pragma unroll
    for (int i = 0; i < 32; i += 8)
        t[ty + i][tx] = W[(size_t)(k0 + ty + i) * N + n0 + tx];
    __syncthreads();
#pragma unroll
    for (int i = 0; i < 32; i += 8) {
        float x = t[tx][ty + i];
        __nv_bfloat16 h = __float2bfloat16_rn(x);
        __nv_bfloat16 l = __float2bfloat16_rn(x - __bfloat162float(h));
        const size_t idx = (size_t)(n0 + ty + i) * K + k0 + tx;
        Whi[idx] = h;
        Wlo[idx] = l;
    }
}

// ---------------------------------------------------------------------------
// RMSNorm + rotary; emits split-bf16 q (pre-scaled), k, and v planes.
// ---------------------------------------------------------------------------
__global__ __launch_bounds__(256) void rms_rope_split(
    const float* __restrict__ qkv,
    const float* __restrict__ gq, const float* __restrict__ gk,
    const float* __restrict__ fcos, const float* __restrict__ fsin,
    __nv_bfloat16* __restrict__ qh, __nv_bfloat16* __restrict__ ql,
    __nv_bfloat16* __restrict__ kh, __nv_bfloat16* __restrict__ kl,
    __nv_bfloat16* __restrict__ vh, __nv_bfloat16* __restrict__ vl)
{
    const int t   = blockIdx.x;
    const int l   = t & (SEQ - 1);
    const int tid = threadIdx.x;

    const float* qrow = qkv + (size_t)t * QKV_COLS;
    const float* krow = qrow + DIMN;
    const float* vrow = qrow + 2 * DIMN;

    float sq = 0.0f, sk = 0.0f;
    for (int i = tid; i < DIMN; i += 256) {
        float a = qrow[i]; sq = fmaf(a, a, sq);
        float b = krow[i]; sk = fmaf(b, b, sk);
    }
#pragma unroll
    for (int off = 16; off; off >>= 1) {
        sq += __shfl_xor_sync(0xffffffffu, sq, off);
        sk += __shfl_xor_sync(0xffffffffu, sk, off);
    }
    __shared__ float redq[8], redk[8];
    __shared__ float bq, bk;
    const int warp = tid >> 5, lane = tid & 31;
    if (lane == 0) { redq[warp] = sq; redk[warp] = sk; }
    __syncthreads();
    if (tid == 0) {
        float a = 0.0f, b = 0.0f;
#pragma unroll
        for (int w = 0; w < 8; ++w) { a += redq[w]; b += redk[w]; }
        bq = a; bk = b;
    }
    __syncthreads();
    const float rq = rsqrtf(bq * (1.0f / DIMN) + EPSV);
    const float rk = rsqrtf(bk * (1.0f / DIMN) + EPSV);

    const size_t ob = (size_t)t * DIMN;
    for (int p = tid; p < DIMN / 2; p += 256) {
        const int head = p >> 6;
        const int i2   = (p & 63) * 2;
        const int ce   = head * HDIM + i2;
        const int co   = ce + 1;
        const float ccos = fcos[l * HDIM + i2];
        const float csin = fsin[l * HDIM + i2 + 1];

        float xe = qrow[ce] * rq * gq[ce];
        float xo = qrow[co] * rq * gq[co];
        float qe = (xe * ccos - xo * csin) * SCALEV;
        float qo = (xe * csin + xo * ccos) * SCALEV;
        uint32_t H, L;
        bsplit2(qe, qo, H, L);
        *(uint32_t*)(qh + ob + ce) = H;
        *(uint32_t*)(ql + ob + ce) = L;

        xe = krow[ce] * rk * gk[ce];
        xo = krow[co] * rk * gk[co];
        float ke = xe * ccos - xo * csin;
        float ko = xe * csin + xo * ccos;
        bsplit2(ke, ko, H, L);
        *(uint32_t*)(kh + ob + ce) = H;
        *(uint32_t*)(kl + ob + ce) = L;

        float v0 = vrow[ce], v1 = vrow[co];
        bsplit2(v0, v1, H, L);
        *(uint32_t*)(vh + ob + ce) = H;
        *(uint32_t*)(vl + ob + ce) = L;
    }
}

// ---------------------------------------------------------------------------
// Tensor-core flash attention. Br=128, Bc=64, D=128.
// ---------------------------------------------------------------------------
__global__ __launch_bounds__(256, 1) void flash_mma(
    const __nv_bfloat16* __restrict__ qhp, const __nv_bfloat16* __restrict__ qlp,
    const __nv_bfloat16* __restrict__ khp, const __nv_bfloat16* __restrict__ klp,
    const __nv_bfloat16* __restrict__ vhp, const __nv_bfloat16* __restrict__ vlp,
    __nv_bfloat16* __restrict__ ohi, __nv_bfloat16* __restrict__ olo)
{
    extern __shared__ char fsm[];
    const uint32_t sb = smem_u32(fsm);

    const int qb = blockIdx.x, bh = blockIdx.y;
    const int b  = bh / NHEADS, h = bh % NHEADS;
    const int tid = threadIdx.x, wid = tid >> 5, lane = tid & 31;
    const int gid = lane >> 2, tig = lane & 3;
    const int l15 = lane & 15;
    const int hofs = h * HDIM;
    const size_t qrow0 = (size_t)(b * SEQ + qb * FBR);
    const size_t krow0 = (size_t)(b * SEQ);

    for (int i = 0; i < 16; ++i) {
        const int idx = tid + 256 * i;
        const int pl  = idx >> 11;
        const int r   = (idx >> 4) & 127;
        const int c   = idx & 15;
        const __nv_bfloat16* src = (pl ? qlp : qhp) + (qrow0 + r) * DIMN + hofs + c * 8;
        cp16(sb + pl * FQPL + r * FROWB + c * 16, src);
    }
    auto loadkv = [&](int s, int kb) {
        const uint32_t st = sb + 2 * FQPL + s * FSTG;
        const size_t kr = krow0 + (size_t)kb * FBC;
        for (int i = 0; i < 16; ++i) {
            const int idx = tid + 256 * i;
            const int pl  = idx >> 10;
            const int r   = (idx >> 4) & 63;
            const int c   = idx & 15;
            const __nv_bfloat16* base = (pl == 0) ? khp : (pl == 1) ? klp
                                      : (pl == 2) ? vhp : vlp;
            cp16(st + pl * FKPL + r * FROWB + c * 16, base + (kr + r) * DIMN + hofs + c * 8);
        }
        cp_commit();
    };
    loadkv(0, 0);
    loadkv(1, 1);

    float oacc[16][4];
#pragma unroll
    for (int d = 0; d < 16; ++d)
#pragma unroll
        for (int c = 0; c < 4; ++c) oacc[d][c] = 0.0f;
    float mrow[2] = {-1e30f, -1e30f};
    float lrow[2] = {0.0f, 0.0f};

    const int qrow = wid * 16 + l15;
    const uint32_t qcol = ((lane >> 4) & 1) * 16;
    const int krw  = l15 & 7;
    const uint32_t kcadd = ((l15 >> 3) & 1) * 16;

    for (int kb = 0; kb < SEQ / FBC; ++kb) {
        cp_wait1();
        __syncthreads();
        const uint32_t st = sb + 2 * FQPL + (kb & 1) * FSTG;
        const uint32_t kh = st, kl = st + FKPL, vh = st + 2 * FKPL, vl = st + 3 * FKPL;

        float sacc[8][4];
#pragma unroll
        for (int nt = 0; nt < 8; ++nt)
#pragma unroll
            for (int c = 0; c < 4; ++c) sacc[nt][c] = 0.0f;

#pragma unroll
        for (int kc = 0; kc < 8; ++kc) {
            uint32_t aqh[4], aql[4];
            ldsm_x4(aqh, sb + qrow * FROWB + kc * 32 + qcol);
            ldsm_x4(aql, sb + FQPL + qrow * FROWB + kc * 32 + qcol);
            const uint32_t kcol = kc * 32 + kcadd;
#pragma unroll
            for (int nt = 0; nt < 8; ++nt) {
                uint32_t bkh[2], bkl[2];
                ldsm_x2(bkh, kh + (nt * 8 + krw) * FROWB + kcol);
                ldsm_x2(bkl, kl + (nt * 8 + krw) * FROWB + kcol);
                mma_bf16(sacc[nt], aqh, bkh);
                mma_bf16(sacc[nt], aqh, bkl);
                mma_bf16(sacc[nt], aql, bkh);
            }
        }

        float mx0 = sacc[0][0], mx1 = sacc[0][2];
#pragma unroll
        for (int nt = 0; nt < 8; ++nt) {
            mx0 = fmaxf(mx0, fmaxf(sacc[nt][0], sacc[nt][1]));
            mx1 = fmaxf(mx1, fmaxf(sacc[nt][2], sacc[nt][3]));
        }
        mx0 = fmaxf(mx0, __shfl_xor_sync(0xffffffffu, mx0, 1));
        mx0 = fmaxf(mx0, __shfl_xor_sync(0xffffffffu, mx0, 2));
        mx1 = fmaxf(mx1, __shfl_xor_sync(0xffffffffu, mx1, 1));
        mx1 = fmaxf(mx1, __shfl_xor_sync(0xffffffffu, mx1, 2));
        const float mn0 = fmaxf(mrow[0], mx0);
        const float mn1 = fmaxf(mrow[1], mx1);
        const float al0 = __expf(mrow[0] - mn0);
        const float al1 = __expf(mrow[1] - mn1);
        mrow[0] = mn0; mrow[1] = mn1;

        float rs0 = 0.0f, rs1 = 0.0f;
#pragma unroll
        for (int nt = 0; nt < 8; ++nt) {
            sacc[nt][0] = __expf(sacc[nt][0] - mn0);
            sacc[nt][1] = __expf(sacc[nt][1] - mn0);
            sacc[nt][2] = __expf(sacc[nt][2] - mn1);
            sacc[nt][3] = __expf(sacc[nt][3] - mn1);
            rs0 += sacc[nt][0] + sacc[nt][1];
            rs1 += sacc[nt][2] + sacc[nt][3];
        }
        rs0 += __shfl_xor_sync(0xffffffffu, rs0, 1);
        rs0 += __shfl_xor_sync(0xffffffffu, rs0, 2);
        rs1 += __shfl_xor_sync(0xffffffffu, rs1, 1);
        rs1 += __shfl_xor_sync(0xffffffffu, rs1, 2);
        lrow[0] = lrow[0] * al0 + rs0;
        lrow[1] = lrow[1] * al1 + rs1;
#pragma unroll
        for (int d = 0; d < 16; ++d) {
            oacc[d][0] *= al0; oacc[d][1] *= al0;
            oacc[d][2] *= al1; oacc[d][3] *= al1;
        }

#pragma unroll
        for (int kc2 = 0; kc2 < 4; ++kc2) {
            uint32_t aph[4], apl[4];
            bsplit2(sacc[2 * kc2][0],     sacc[2 * kc2][1],     aph[0], apl[0]);
            bsplit2(sacc[2 * kc2][2],     sacc[2 * kc2][3],     aph[1], apl[1]);
            bsplit2(sacc[2 * kc2 + 1][0], sacc[2 * kc2 + 1][1], aph[2], apl[2]);
            bsplit2(sacc[2 * kc2 + 1][2], sacc[2 * kc2 + 1][3], aph[3], apl[3]);
            const uint32_t vr = (kc2 * 16 + l15) * FROWB;
#pragma unroll
            for (int dt = 0; dt < 16; ++dt) {
                uint32_t bvh[2], bvl[2];
                ldsm_x2t(bvh, vh + vr + dt * 16);
                ldsm_x2t(bvl, vl + vr + dt * 16);
                mma_bf16(oacc[dt], aph, bvh);
                mma_bf16(oacc[dt], aph, bvl);
                mma_bf16(oacc[dt], apl, bvh);
            }
        }
        __syncthreads();
        if (kb + 2 < SEQ / FBC) loadkv(kb & 1, kb + 2);
    }

#pragma unroll
    for (int i = 0; i < 2; ++i) {
        const float inv = 1.0f / lrow[i];
        const size_t base =
            (qrow0 + (size_t)(wid * 16 + gid + i * 8)) * DIMN + hofs + tig * 2;
#pragma unroll
        for (int dt = 0; dt < 16; ++dt) {
            uint32_t H, L;
            bsplit2(oacc[dt][2 * i] * inv, oacc[dt][2 * i + 1] * inv, H, L);
            *(uint32_t*)(ohi + base + dt * 8) = H;
            *(uint32_t*)(olo + base + dt * 8) = L;
        }
    }
}

// ---------------------------------------------------------------------------
extern "C" void kernel_launch(void* const* d_in, const int* in_sizes, int n_in,
                              void* d_out, int out_size)
{
    const float* X    = (const float*)d_in[0];
    const float* fcos = (const float*)d_in[1];
    const float* fsin = (const float*)d_in[2];
    const float* Wqkv = (const float*)d_in[3];
    const float* bqkv = (const float*)d_in[4];
    const float* gq   = (const float*)d_in[5];
    const float* gk   = (const float*)d_in[6];
    const float* Wout = (const float*)d_in[7];
    const float* bout = (const float*)d_in[8];
    float* out = (float*)d_out;

    float *qkvbuf;
    __nv_bfloat16 *xhi, *xlo, *ahi, *alo, *wqhi, *wqlo, *wohi, *wolo;
    __nv_bfloat16 *qh, *ql, *kh, *kl, *vh, *vl;
    cudaGetSymbolAddress((void**)&qkvbuf, g_qkv);
    cudaGetSymbolAddress((void**)&xhi, g_xhi);
    cudaGetSymbolAddress((void**)&xlo, g_xlo);
    cudaGetSymbolAddress((void**)&ahi, g_ahi);
    cudaGetSymbolAddress((void**)&alo, g_alo);
    cudaGetSymbolAddress((void**)&wqhi, g_wqhi);
    cudaGetSymbolAddress((void**)&wqlo, g_wqlo);
    cudaGetSymbolAddress((void**)&wohi, g_wohi);
    cudaGetSymbolAddress((void**)&wolo, g_wolo);
    cudaGetSymbolAddress((void**)&qh, g_qh);
    cudaGetSymbolAddress((void**)&ql, g_ql);
    cudaGetSymbolAddress((void**)&kh, g_kh);
    cudaGetSymbolAddress((void**)&kl, g_kl);
    cudaGetSymbolAddress((void**)&vh, g_vh);
    cudaGetSymbolAddress((void**)&vl, g_vl);

    cudaFuncSetAttribute(gemm_bf16x3, cudaFuncAttributeMaxDynamicSharedMemorySize, GSMEM);
    cudaFuncSetAttribute(flash_mma, cudaFuncAttributeMaxDynamicSharedMemorySize, FSMEM);

    // 0) precision-split operands
    split_bf16<<<(TOKENS * DIMN / 4 + 255) / 256, 256>>>(
        (const float4*)X, (uint2*)xhi, (uint2*)xlo, TOKENS * DIMN / 4);
    transpose_split<<<dim3(QKV_COLS / 32, DIMN / 32), dim3(32, 8)>>>(
        Wqkv, wqhi, wqlo, DIMN, QKV_COLS);
    transpose_split<<<dim3(DIMN / 32, DIMN / 32), dim3(32, 8)>>>(
        Wout, wohi, wolo, DIMN, DIMN);

    // 1) qkv = X @ W_qkv + b_qkv
    gemm_bf16x3<<<dim3(TOKENS / GBM, QKV_COLS / GBN), 256, GSMEM>>>(
        xhi, xlo, wqhi, wqlo, bqkv, qkvbuf, QKV_COLS);

    // 2) RMSNorm + RoPE -> split planes
    rms_rope_split<<<TOKENS, 256>>>(qkvbuf, gq, gk, fcos, fsin,
                                    qh, ql, kh, kl, vh, vl);

    // 3) tensor-core flash attention -> bf16 hi/lo planes
    flash_mma<<<dim3(SEQ / FBR, BATCH * NHEADS), 256, FSMEM>>>(
        qh, ql, kh, kl, vh, vl, ahi, alo);

    // 4) out = attn @ W_out + b_out
    gemm_bf16x3<<<dim3(TOKENS / GBM, DIMN / GBN), 256, GSMEM>>>(
        ahi, alo, wohi, wolo, bout, out, DIMN);
}

// round 9
// speedup vs baseline: 2.1819x; 1.1073x over previous
#include <cuda_runtime.h>
#include <cuda_bf16.h>
#include <math.h>
#include <stdint.h>

// Problem constants
#define DIMN     5120
#define NHEADS   40
#define HDIM     128
#define BATCH    2
#define SEQ      1024
#define TOKENS   (BATCH * SEQ)        // 2048
#define QKV_COLS (3 * DIMN)           // 15360
#define EPSV     1e-6f
#define SCALEV   0.08838834764831845f // 128^-0.5

// GEMM tiling: CTA 128x128, 8 warps of 64x32, BK=32, 2 stages, 2 CTAs/SM
#define GBM 128
#define GBN 128
#define GBK 32
#define GSTAGES 2
#define AROW 40                               // (32+8) bf16 per row
#define AROWB (AROW * 2)                      // 80 bytes
#define A_PLANE (GBM * AROWB)                 // 10240 B
#define B_PLANE (GBN * AROWB)                 // 10240 B
#define STAGE_B (2 * A_PLANE + 2 * B_PLANE)   // 40960
#define GSMEM (GSTAGES * STAGE_B)             // 81920 (2 CTAs fit per SM)
#define NCHUNK (DIMN / GBK)                   // 160

// Flash tiling: Br=128 (8 warps x m16), Bc=64, D=128, 2-stage cp.async K/V
#define FBR 128
#define FBC 64
#define FROWB 272                             // 128 bf16 * 2B + 16B pad
#define FQPL (FBR * FROWB)                    // 34816
#define FKPL (FBC * FROWB)                    // 17408
#define FSTG (4 * FKPL)                       // 69632 (khi,klo,vhi,vlo)
#define FSMEM (2 * FQPL + 2 * FSTG)           // 208896

// Scratch (no allocations allowed)
__device__ float          g_qkv[(size_t)TOKENS * QKV_COLS];
__device__ __nv_bfloat16  g_xhi[(size_t)TOKENS * DIMN];
__device__ __nv_bfloat16  g_xlo[(size_t)TOKENS * DIMN];
__device__ __nv_bfloat16  g_ahi[(size_t)TOKENS * DIMN];
__device__ __nv_bfloat16  g_alo[(size_t)TOKENS * DIMN];
__device__ __nv_bfloat16  g_wqhi[(size_t)QKV_COLS * DIMN];
__device__ __nv_bfloat16  g_wqlo[(size_t)QKV_COLS * DIMN];
__device__ __nv_bfloat16  g_wohi[(size_t)DIMN * DIMN];
__device__ __nv_bfloat16  g_wolo[(size_t)DIMN * DIMN];
__device__ __nv_bfloat16  g_qh[(size_t)TOKENS * DIMN];
__device__ __nv_bfloat16  g_ql[(size_t)TOKENS * DIMN];
__device__ __nv_bfloat16  g_kh[(size_t)TOKENS * DIMN];
__device__ __nv_bfloat16  g_kl[(size_t)TOKENS * DIMN];
__device__ __nv_bfloat16  g_vh[(size_t)TOKENS * DIMN];
__device__ __nv_bfloat16  g_vl[(size_t)TOKENS * DIMN];

// ---------------------------------------------------------------------------
__device__ __forceinline__ uint32_t smem_u32(const void* p) {
    uint32_t a;
    asm("{ .reg .u64 t; cvta.to.shared.u64 t, %1; cvt.u32.u64 %0, t; }" : "=r"(a) : "l"(p));
    return a;
}
__device__ __forceinline__ void cp16(uint32_t s, const void* g) {
    asm volatile("cp.async.cg.shared.global [%0], [%1], 16;" :: "r"(s), "l"(g));
}
__device__ __forceinline__ void cp_commit() {
    asm volatile("cp.async.commit_group;" ::: "memory");
}
__device__ __forceinline__ void cp_wait1() {
    asm volatile("cp.async.wait_group 1;" ::: "memory");
}
__device__ __forceinline__ void mma_bf16(float* c, const uint32_t* a, const uint32_t* b) {
    asm volatile("mma.sync.aligned.m16n8k16.row.col.f32.bf16.bf16.f32 "
        "{%0,%1,%2,%3}, {%4,%5,%6,%7}, {%8,%9}, {%0,%1,%2,%3};"
        : "+f"(c[0]), "+f"(c[1]), "+f"(c[2]), "+f"(c[3])
        : "r"(a[0]), "r"(a[1]), "r"(a[2]), "r"(a[3]), "r"(b[0]), "r"(b[1]));
}
__device__ __forceinline__ void ldsm_x4(uint32_t* r, uint32_t a) {
    asm volatile("ldmatrix.sync.aligned.m8n8.x4.shared.b16 {%0,%1,%2,%3}, [%4];"
        : "=r"(r[0]), "=r"(r[1]), "=r"(r[2]), "=r"(r[3]) : "r"(a));
}
__device__ __forceinline__ void ldsm_x2(uint32_t* r, uint32_t a) {
    asm volatile("ldmatrix.sync.aligned.m8n8.x2.shared.b16 {%0,%1}, [%2];"
        : "=r"(r[0]), "=r"(r[1]) : "r"(a));
}
__device__ __forceinline__ void ldsm_x2t(uint32_t* r, uint32_t a) {
    asm volatile("ldmatrix.sync.aligned.m8n8.x2.trans.shared.b16 {%0,%1}, [%2];"
        : "=r"(r[0]), "=r"(r[1]) : "r"(a));
}
__device__ __forceinline__ void bsplit2(float x, float y, uint32_t& hi, uint32_t& lo) {
    __nv_bfloat16 hx = __float2bfloat16_rn(x), hy = __float2bfloat16_rn(y);
    __nv_bfloat16 lx = __float2bfloat16_rn(x - __bfloat162float(hx));
    __nv_bfloat16 ly = __float2bfloat16_rn(y - __bfloat162float(hy));
    hi = ((uint32_t)__bfloat16_as_ushort(hy) << 16) | __bfloat16_as_ushort(hx);
    lo = ((uint32_t)__bfloat16_as_ushort(ly) << 16) | __bfloat16_as_ushort(lx);
}

// ---------------------------------------------------------------------------
// GEMM: C[M, Ntot] = A @ B^T + bias, 3-pass split bf16 (hh + hl + lh).
// CTA 128x128, 2 CTAs/SM for tensor-pipe overlap. ldmatrix fragments.
// ---------------------------------------------------------------------------
__global__ __launch_bounds__(256, 2) void gemm_bf16x3(
    const __nv_bfloat16* __restrict__ Ahi, const __nv_bfloat16* __restrict__ Alo,
    const __nv_bfloat16* __restrict__ Bhi, const __nv_bfloat16* __restrict__ Blo,
    const float* __restrict__ bias, float* __restrict__ C, int Ntot)
{
    extern __shared__ char gsm[];
    const uint32_t sbase = smem_u32(gsm);
    const int tid = threadIdx.x;
    const int m0  = blockIdx.x * GBM;
    const int n0  = blockIdx.y * GBN;
    const int K   = DIMN;

    const int wid  = tid >> 5, lane = tid & 31;
    const int wm   = wid & 1;        // 2 groups of 64 rows
    const int wn   = wid >> 1;       // 4 groups of 32 cols
    const int gid  = lane >> 2;
    const int tig  = lane & 3;
    const int l15  = lane & 15;

    const uint32_t a_row  = (uint32_t)(wm * 64 + l15);
    const uint32_t a_colh = (uint32_t)((lane >> 4) << 4);
    const uint32_t b_row  = (uint32_t)(wn * 32 + (lane & 7));
    const uint32_t b_colh = (uint32_t)(((lane >> 3) & 1) << 4);

    float acc[4][4][4];
#pragma unroll
    for (int a = 0; a < 4; ++a)
#pragma unroll
        for (int b = 0; b < 4; ++b)
#pragma unroll
            for (int c = 0; c < 4; ++c) acc[a][b][c] = 0.0f;

    auto issue = [&](int s, int k0) {
        const uint32_t st = sbase + s * STAGE_B;
        // A: 2 planes x 512 chunks; B: 2 planes x 512 chunks; 8 cp16/thread
#pragma unroll
        for (int i = 0; i < 4; ++i) {
            const int idx = tid + 256 * i;        // 0..1023
            const int p   = idx >> 9;
            const int r   = (idx >> 2) & 127;
            const int ch  = idx & 3;
            const __nv_bfloat16* src = (p ? Alo : Ahi) + (size_t)(m0 + r) * K + k0 + ch * 8;
            cp16(st + p * A_PLANE + r * AROWB + ch * 16, src);
        }
#pragma unroll
        for (int i = 0; i < 4; ++i) {
            const int idx = tid + 256 * i;
            const int p   = idx >> 9;
            const int r   = (idx >> 2) & 127;
            const int ch  = idx & 3;
            const __nv_bfloat16* src = (p ? Blo : Bhi) + (size_t)(n0 + r) * K + k0 + ch * 8;
            cp16(st + 2 * A_PLANE + p * B_PLANE + r * AROWB + ch * 16, src);
        }
        cp_commit();
    };

    issue(0, 0);
    issue(1, GBK);

    for (int it = 0; it < NCHUNK; ++it) {
        cp_wait1();
        __syncthreads();
        const uint32_t ss = sbase + (it & 1) * STAGE_B;

#pragma unroll
        for (int ks = 0; ks < 2; ++ks) {
            const uint32_t kofs = (uint32_t)(ks * 32);

            uint32_t ah[4][4], al[4][4];
#pragma unroll
            for (int mt = 0; mt < 4; ++mt) {
                const uint32_t aaddr = ss + (a_row + mt * 16) * AROWB + kofs + a_colh;
                ldsm_x4(ah[mt], aaddr);
                ldsm_x4(al[mt], aaddr + A_PLANE);
            }
            uint32_t bh[4][2], bl[4][2];
#pragma unroll
            for (int nt = 0; nt < 4; ++nt) {
                const uint32_t baddr =
                    ss + 2 * A_PLANE + (b_row + nt * 8) * AROWB + kofs + b_colh;
                ldsm_x2(bh[nt], baddr);
                ldsm_x2(bl[nt], baddr + B_PLANE);
            }
            // pass-major: consecutive MMAs hit different accumulators
#pragma unroll
            for (int mt = 0; mt < 4; ++mt)
#pragma unroll
                for (int nt = 0; nt < 4; ++nt)
                    mma_bf16(acc[mt][nt], ah[mt], bh[nt]);
#pragma unroll
            for (int mt = 0; mt < 4; ++mt)
#pragma unroll
                for (int nt = 0; nt < 4; ++nt)
                    mma_bf16(acc[mt][nt], ah[mt], bl[nt]);
#pragma unroll
            for (int mt = 0; mt < 4; ++mt)
#pragma unroll
                for (int nt = 0; nt < 4; ++nt)
                    mma_bf16(acc[mt][nt], al[mt], bh[nt]);
        }
        __syncthreads();
        if (it + 2 < NCHUNK) issue(it & 1, (it + 2) * GBK);
    }

#pragma unroll
    for (int mt = 0; mt < 4; ++mt) {
#pragma unroll
        for (int nt = 0; nt < 4; ++nt) {
            const int row = m0 + wm * 64 + mt * 16 + gid;
            const int col = n0 + wn * 32 + nt * 8 + tig * 2;
            const float b0 = bias[col], b1 = bias[col + 1];
            float2 v0 = {acc[mt][nt][0] + b0, acc[mt][nt][1] + b1};
            float2 v1 = {acc[mt][nt][2] + b0, acc[mt][nt][3] + b1};
            *(float2*)(C + (size_t)row * Ntot + col)       = v0;
            *(float2*)(C + (size_t)(row + 8) * Ntot + col) = v1;
        }
    }
}

// ---------------------------------------------------------------------------
__global__ __launch_bounds__(256) void split_bf16(
    const float4* __restrict__ in, uint2* __restrict__ hi, uint2* __restrict__ lo, int n4)
{
    const int i = blockIdx.x * 256 + threadIdx.x;
    if (i >= n4) return;
    float4 v = in[i];
    uint32_t H0, L0, H1, L1;
    bsplit2(v.x, v.y, H0, L0);
    bsplit2(v.z, v.w, H1, L1);
    hi[i] = make_uint2(H0, H1);
    lo[i] = make_uint2(L0, L1);
}

__global__ __launch_bounds__(256) void transpose_split(
    const float* __restrict__ W,
    __nv_bfloat16* __restrict__ Whi, __nv_bfloat16* __restrict__ Wlo, int K, int N)
{
    __shared__ float t[32][33];
    const int n0 = blockIdx.x * 32, k0 = blockIdx.y * 32;
    const int tx = threadIdx.x, ty = threadIdx.y;
#pragma unroll
    for (int i = 0; i < 32; i += 8)
        t[ty + i][tx] = W[(size_t)(k0 + ty + i) * N + n0 + tx];
    __syncthreads();
#pragma unroll
    for (int i = 0; i < 32; i += 8) {
        float x = t[tx][ty + i];
        __nv_bfloat16 h = __float2bfloat16_rn(x);
        __nv_bfloat16 l = __float2bfloat16_rn(x - __bfloat162float(h));
        const size_t idx = (size_t)(n0 + ty + i) * K + k0 + tx;
        Whi[idx] = h;
        Wlo[idx] = l;
    }
}

// ---------------------------------------------------------------------------
// RMSNorm + rotary; emits split-bf16 q (pre-scaled), k, and v planes.
// ---------------------------------------------------------------------------
__global__ __launch_bounds__(256) void rms_rope_split(
    const float* __restrict__ qkv,
    const float* __restrict__ gq, const float* __restrict__ gk,
    const float* __restrict__ fcos, const float* __restrict__ fsin,
    __nv_bfloat16* __restrict__ qh, __nv_bfloat16* __restrict__ ql,
    __nv_bfloat16* __restrict__ kh, __nv_bfloat16* __restrict__ kl,
    __nv_bfloat16* __restrict__ vh, __nv_bfloat16* __restrict__ vl)
{
    const int t   = blockIdx.x;
    const int l   = t & (SEQ - 1);
    const int tid = threadIdx.x;

    const float* qrow = qkv + (size_t)t * QKV_COLS;
    const float* krow = qrow + DIMN;
    const float* vrow = qrow + 2 * DIMN;

    float sq = 0.0f, sk = 0.0f;
    for (int i = tid; i < DIMN; i += 256) {
        float a = qrow[i]; sq = fmaf(a, a, sq);
        float b = krow[i]; sk = fmaf(b, b, sk);
    }
#pragma unroll
    for (int off = 16; off; off >>= 1) {
        sq += __shfl_xor_sync(0xffffffffu, sq, off);
        sk += __shfl_xor_sync(0xffffffffu, sk, off);
    }
    __shared__ float redq[8], redk[8];
    __shared__ float bq, bk;
    const int warp = tid >> 5, lane = tid & 31;
    if (lane == 0) { redq[warp] = sq; redk[warp] = sk; }
    __syncthreads();
    if (tid == 0) {
        float a = 0.0f, b = 0.0f;
#pragma unroll
        for (int w = 0; w < 8; ++w) { a += redq[w]; b += redk[w]; }
        bq = a; bk = b;
    }
    __syncthreads();
    const float rq = rsqrtf(bq * (1.0f / DIMN) + EPSV);
    const float rk = rsqrtf(bk * (1.0f / DIMN) + EPSV);

    const size_t ob = (size_t)t * DIMN;
    for (int p = tid; p < DIMN / 2; p += 256) {
        const int head = p >> 6;
        const int i2   = (p & 63) * 2;
        const int ce   = head * HDIM + i2;
        const int co   = ce + 1;
        const float ccos = fcos[l * HDIM + i2];
        const float csin = fsin[l * HDIM + i2 + 1];

        float xe = qrow[ce] * rq * gq[ce];
        float xo = qrow[co] * rq * gq[co];
        float qe = (xe * ccos - xo * csin) * SCALEV;
        float qo = (xe * csin + xo * ccos) * SCALEV;
        uint32_t H, L;
        bsplit2(qe, qo, H, L);
        *(uint32_t*)(qh + ob + ce) = H;
        *(uint32_t*)(ql + ob + ce) = L;

        xe = krow[ce] * rk * gk[ce];
        xo = krow[co] * rk * gk[co];
        float ke = xe * ccos - xo * csin;
        float ko = xe * csin + xo * ccos;
        bsplit2(ke, ko, H, L);
        *(uint32_t*)(kh + ob + ce) = H;
        *(uint32_t*)(kl + ob + ce) = L;

        float v0 = vrow[ce], v1 = vrow[co];
        bsplit2(v0, v1, H, L);
        *(uint32_t*)(vh + ob + ce) = H;
        *(uint32_t*)(vl + ob + ce) = L;
    }
}

// ---------------------------------------------------------------------------
// Tensor-core flash attention. Br=128, Bc=64, D=128.
// ---------------------------------------------------------------------------
__global__ __launch_bounds__(256, 1) void flash_mma(
    const __nv_bfloat16* __restrict__ qhp, const __nv_bfloat16* __restrict__ qlp,
    const __nv_bfloat16* __restrict__ khp, const __nv_bfloat16* __restrict__ klp,
    const __nv_bfloat16* __restrict__ vhp, const __nv_bfloat16* __restrict__ vlp,
    __nv_bfloat16* __restrict__ ohi, __nv_bfloat16* __restrict__ olo)
{
    extern __shared__ char fsm[];
    const uint32_t sb = smem_u32(fsm);

    const int qb = blockIdx.x, bh = blockIdx.y;
    const int b  = bh / NHEADS, h = bh % NHEADS;
    const int tid = threadIdx.x, wid = tid >> 5, lane = tid & 31;
    const int gid = lane >> 2, tig = lane & 3;
    const int l15 = lane & 15;
    const int hofs = h * HDIM;
    const size_t qrow0 = (size_t)(b * SEQ + qb * FBR);
    const size_t krow0 = (size_t)(b * SEQ);

    for (int i = 0; i < 16; ++i) {
        const int idx = tid + 256 * i;
        const int pl  = idx >> 11;
        const int r   = (idx >> 4) & 127;
        const int c   = idx & 15;
        const __nv_bfloat16* src = (pl ? qlp : qhp) + (qrow0 + r) * DIMN + hofs + c * 8;
        cp16(sb + pl * FQPL + r * FROWB + c * 16, src);
    }
    auto loadkv = [&](int s, int kb) {
        const uint32_t st = sb + 2 * FQPL + s * FSTG;
        const size_t kr = krow0 + (size_t)kb * FBC;
        for (int i = 0; i < 16; ++i) {
            const int idx = tid + 256 * i;
            const int pl  = idx >> 10;
            const int r   = (idx >> 4) & 63;
            const int c   = idx & 15;
            const __nv_bfloat16* base = (pl == 0) ? khp : (pl == 1) ? klp
                                      : (pl == 2) ? vhp : vlp;
            cp16(st + pl * FKPL + r * FROWB + c * 16, base + (kr + r) * DIMN + hofs + c * 8);
        }
        cp_commit();
    };
    loadkv(0, 0);
    loadkv(1, 1);

    float oacc[16][4];
#pragma unroll
    for (int d = 0; d < 16; ++d)
#pragma unroll
        for (int c = 0; c < 4; ++c) oacc[d][c] = 0.0f;
    float mrow[2] = {-1e30f, -1e30f};
    float lrow[2] = {0.0f, 0.0f};

    const int qrow = wid * 16 + l15;
    const uint32_t qcol = ((lane >> 4) & 1) * 16;
    const int krw  = l15 & 7;
    const uint32_t kcadd = ((l15 >> 3) & 1) * 16;

    for (int kb = 0; kb < SEQ / FBC; ++kb) {
        cp_wait1();
        __syncthreads();
        const uint32_t st = sb + 2 * FQPL + (kb & 1) * FSTG;
        const uint32_t kh = st, kl = st + FKPL, vh = st + 2 * FKPL, vl = st + 3 * FKPL;

        float sacc[8][4];
#pragma unroll
        for (int nt = 0; nt < 8; ++nt)
#pragma unroll
            for (int c = 0; c < 4; ++c) sacc[nt][c] = 0.0f;

#pragma unroll
        for (int kc = 0; kc < 8; ++kc) {
            uint32_t aqh[4], aql[4];
            ldsm_x4(aqh, sb + qrow * FROWB + kc * 32 + qcol);
            ldsm_x4(aql, sb + FQPL + qrow * FROWB + kc * 32 + qcol);
            const uint32_t kcol = kc * 32 + kcadd;
#pragma unroll
            for (int nt = 0; nt < 8; ++nt) {
                uint32_t bkh[2], bkl[2];
                ldsm_x2(bkh, kh + (nt * 8 + krw) * FROWB + kcol);
                ldsm_x2(bkl, kl + (nt * 8 + krw) * FROWB + kcol);
                mma_bf16(sacc[nt], aqh, bkh);
                mma_bf16(sacc[nt], aqh, bkl);
                mma_bf16(sacc[nt], aql, bkh);
            }
        }

        float mx0 = sacc[0][0], mx1 = sacc[0][2];
#pragma unroll
        for (int nt = 0; nt < 8; ++nt) {
            mx0 = fmaxf(mx0, fmaxf(sacc[nt][0], sacc[nt][1]));
            mx1 = fmaxf(mx1, fmaxf(sacc[nt][2], sacc[nt][3]));
        }
        mx0 = fmaxf(mx0, __shfl_xor_sync(0xffffffffu, mx0, 1));
        mx0 = fmaxf(mx0, __shfl_xor_sync(0xffffffffu, mx0, 2));
        mx1 = fmaxf(mx1, __shfl_xor_sync(0xffffffffu, mx1, 1));
        mx1 = fmaxf(mx1, __shfl_xor_sync(0xffffffffu, mx1, 2));
        const float mn0 = fmaxf(mrow[0], mx0);
        const float mn1 = fmaxf(mrow[1], mx1);
        const float al0 = __expf(mrow[0] - mn0);
        const float al1 = __expf(mrow[1] - mn1);
        mrow[0] = mn0; mrow[1] = mn1;

        float rs0 = 0.0f, rs1 = 0.0f;
#pragma unroll
        for (int nt = 0; nt < 8; ++nt) {
            sacc[nt][0] = __expf(sacc[nt][0] - mn0);
            sacc[nt][1] = __expf(sacc[nt][1] - mn0);
            sacc[nt][2] = __expf(sacc[nt][2] - mn1);
            sacc[nt][3] = __expf(sacc[nt][3] - mn1);
            rs0 += sacc[nt][0] + sacc[nt][1];
            rs1 += sacc[nt][2] + sacc[nt][3];
        }
        rs0 += __shfl_xor_sync(0xffffffffu, rs0, 1);
        rs0 += __shfl_xor_sync(0xffffffffu, rs0, 2);
        rs1 += __shfl_xor_sync(0xffffffffu, rs1, 1);
        rs1 += __shfl_xor_sync(0xffffffffu, rs1, 2);
        lrow[0] = lrow[0] * al0 + rs0;
        lrow[1] = lrow[1] * al1 + rs1;
#pragma unroll
        for (int d = 0; d < 16; ++d) {
            oacc[d][0] *= al0; oacc[d][1] *= al0;
            oacc[d][2] *= al1; oacc[d][3] *= al1;
        }

#pragma unroll
        for (int kc2 = 0; kc2 < 4; ++kc2) {
            uint32_t aph[4], apl[4];
            bsplit2(sacc[2 * kc2][0],     sacc[2 * kc2][1],     aph[0], apl[0]);
            bsplit2(sacc[2 * kc2][2],     sacc[2 * kc2][3],     aph[1], apl[1]);
            bsplit2(sacc[2 * kc2 + 1][0], sacc[2 * kc2 + 1][1], aph[2], apl[2]);
            bsplit2(sacc[2 * kc2 + 1][2], sacc[2 * kc2 + 1][3], aph[3], apl[3]);
            const uint32_t vr = (kc2 * 16 + l15) * FROWB;
#pragma unroll
            for (int dt = 0; dt < 16; ++dt) {
                uint32_t bvh[2], bvl[2];
                ldsm_x2t(bvh, vh + vr + dt * 16);
                ldsm_x2t(bvl, vl + vr + dt * 16);
                mma_bf16(oacc[dt], aph, bvh);
                mma_bf16(oacc[dt], aph, bvl);
                mma_bf16(oacc[dt], apl, bvh);
            }
        }
        __syncthreads();
        if (kb + 2 < SEQ / FBC) loadkv(kb & 1, kb + 2);
    }

#pragma unroll
    for (int i = 0; i < 2; ++i) {
        const float inv = 1.0f / lrow[i];
        const size_t base =
            (qrow0 + (size_t)(wid * 16 + gid + i * 8)) * DIMN + hofs + tig * 2;
#pragma unroll
        for (int dt = 0; dt < 16; ++dt) {
            uint32_t H, L;
            bsplit2(oacc[dt][2 * i] * inv, oacc[dt][2 * i + 1] * inv, H, L);
            *(uint32_t*)(ohi + base + dt * 8) = H;
            *(uint32_t*)(olo + base + dt * 8) = L;
        }
    }
}

// ---------------------------------------------------------------------------
extern "C" void kernel_launch(void* const* d_in, const int* in_sizes, int n_in,
                              void* d_out, int out_size)
{
    const float* X    = (const float*)d_in[0];
    const float* fcos = (const float*)d_in[1];
    const float* fsin = (const float*)d_in[2];
    const float* Wqkv = (const float*)d_in[3];
    const float* bqkv = (const float*)d_in[4];
    const float* gq   = (const float*)d_in[5];
    const float* gk   = (const float*)d_in[6];
    const float* Wout = (const float*)d_in[7];
    const float* bout = (const float*)d_in[8];
    float* out = (float*)d_out;

    float *qkvbuf;
    __nv_bfloat16 *xhi, *xlo, *ahi, *alo, *wqhi, *wqlo, *wohi, *wolo;
    __nv_bfloat16 *qh, *ql, *kh, *kl, *vh, *vl;
    cudaGetSymbolAddress((void**)&qkvbuf, g_qkv);
    cudaGetSymbolAddress((void**)&xhi, g_xhi);
    cudaGetSymbolAddress((void**)&xlo, g_xlo);
    cudaGetSymbolAddress((void**)&ahi, g_ahi);
    cudaGetSymbolAddress((void**)&alo, g_alo);
    cudaGetSymbolAddress((void**)&wqhi, g_wqhi);
    cudaGetSymbolAddress((void**)&wqlo, g_wqlo);
    cudaGetSymbolAddress((void**)&wohi, g_wohi);
    cudaGetSymbolAddress((void**)&wolo, g_wolo);
    cudaGetSymbolAddress((void**)&qh, g_qh);
    cudaGetSymbolAddress((void**)&ql, g_ql);
    cudaGetSymbolAddress((void**)&kh, g_kh);
    cudaGetSymbolAddress((void**)&kl, g_kl);
    cudaGetSymbolAddress((void**)&vh, g_vh);
    cudaGetSymbolAddress((void**)&vl, g_vl);

    cudaFuncSetAttribute(gemm_bf16x3, cudaFuncAttributeMaxDynamicSharedMemorySize, GSMEM);
    cudaFuncSetAttribute(flash_mma, cudaFuncAttributeMaxDynamicSharedMemorySize, FSMEM);

    // 0) precision-split operands
    split_bf16<<<(TOKENS * DIMN / 4 + 255) / 256, 256>>>(
        (const float4*)X, (uint2*)xhi, (uint2*)xlo, TOKENS * DIMN / 4);
    transpose_split<<<dim3(QKV_COLS / 32, DIMN / 32), dim3(32, 8)>>>(
        Wqkv, wqhi, wqlo, DIMN, QKV_COLS);
    transpose_split<<<dim3(DIMN / 32, DIMN / 32), dim3(32, 8)>>>(
        Wout, wohi, wolo, DIMN, DIMN);

    // 1) qkv = X @ W_qkv + b_qkv
    gemm_bf16x3<<<dim3(TOKENS / GBM, QKV_COLS / GBN), 256, GSMEM>>>(
        xhi, xlo, wqhi, wqlo, bqkv, qkvbuf, QKV_COLS);

    // 2) RMSNorm + RoPE -> split planes
    rms_rope_split<<<TOKENS, 256>>>(qkvbuf, gq, gk, fcos, fsin,
                                    qh, ql, kh, kl, vh, vl);

    // 3) tensor-core flash attention -> bf16 hi/lo planes
    flash_mma<<<dim3(SEQ / FBR, BATCH * NHEADS), 256, FSMEM>>>(
        qh, ql, kh, kl, vh, vl, ahi, alo);

    // 4) out = attn @ W_out + b_out
    gemm_bf16x3<<<dim3(TOKENS / GBM, DIMN / GBN), 256, GSMEM>>>(
        ahi, alo, wohi, wolo, bout, out, DIMN);
}